// round 1
// baseline (speedup 1.0000x reference)
#include <cuda_runtime.h>
#include <math.h>

#define EMBED   1024
#define HEADS   16
#define HD      64
#define BATCH   2
#define SEQ     2048
#define MROWS   (BATCH*SEQ)       /* 4096 */
#define NQKV    (3*EMBED)         /* 3072 */
#define LOG2E   1.44269504088896f

/* Scratch (allocation-free rule: __device__ globals) */
__device__ float g_Q[BATCH*HEADS*SEQ*HD];   /* [b*H+h][s][d], pre-scaled by 1/8 */
__device__ float g_K[BATCH*HEADS*SEQ*HD];
__device__ float g_V[BATCH*HEADS*SEQ*HD];
__device__ float g_A[BATCH*SEQ*EMBED];      /* attention output, [b,s,h*64+d] */

/* ------------------------------------------------------------------ */
/* QKV GEMM: C[m,n] = sum_k X[m,k] * W[n,k];  M=4096, N=3072, K=1024  */
/* Epilogue scatters into g_Q (scaled), g_K, g_V                       */
/* ------------------------------------------------------------------ */
__global__ __launch_bounds__(256) void qkv_gemm(const float* __restrict__ X,
                                                const float* __restrict__ W)
{
    __shared__ float As[8][128];
    __shared__ float Bs[8][128];

    const int bm = blockIdx.y * 128;
    const int bn = blockIdx.x * 128;
    const int tid = threadIdx.x;
    const int tr = tid >> 4;         /* 0..15 */
    const int tc = tid & 15;         /* 0..15 */
    const int lrow = tid >> 1;       /* 0..127 */
    const int lk   = (tid & 1) * 4;  /* 0 or 4 */

    const float* Ap = X + (size_t)(bm + lrow) * 1024 + lk;
    const float* Bp = W + (size_t)(bn + lrow) * 1024 + lk;

    float acc[8][8];
#pragma unroll
    for (int i = 0; i < 8; i++)
#pragma unroll
        for (int j = 0; j < 8; j++) acc[i][j] = 0.f;

    for (int k0 = 0; k0 < 1024; k0 += 8) {
        float4 av = *(const float4*)(Ap + k0);
        float4 bv = *(const float4*)(Bp + k0);
        As[lk+0][lrow] = av.x; As[lk+1][lrow] = av.y;
        As[lk+2][lrow] = av.z; As[lk+3][lrow] = av.w;
        Bs[lk+0][lrow] = bv.x; Bs[lk+1][lrow] = bv.y;
        Bs[lk+2][lrow] = bv.z; Bs[lk+3][lrow] = bv.w;
        __syncthreads();

#pragma unroll
        for (int kk = 0; kk < 8; kk++) {
            float a[8], b[8];
#pragma unroll
            for (int i = 0; i < 8; i++) a[i] = As[kk][tr*8 + i];
#pragma unroll
            for (int j = 0; j < 8; j++) b[j] = Bs[kk][tc*8 + j];
#pragma unroll
            for (int i = 0; i < 8; i++)
#pragma unroll
                for (int j = 0; j < 8; j++)
                    acc[i][j] = fmaf(a[i], b[j], acc[i][j]);
        }
        __syncthreads();
    }

    /* scatter epilogue */
#pragma unroll
    for (int i = 0; i < 8; i++) {
        const int m = bm + tr*8 + i;
        const int b = m >> 11;           /* /2048 */
        const int s = m & 2047;
#pragma unroll
        for (int j = 0; j < 8; j++) {
            const int n = bn + tc*8 + j;
            const int part = n >> 10;
            const int h = (n >> 6) & 15;
            const int d = n & 63;
            const size_t idx = (((size_t)(b*HEADS + h))*SEQ + s)*HD + d;
            const float v = acc[i][j];
            if (part == 0)      g_Q[idx] = v * 0.125f;   /* fold 1/sqrt(64) */
            else if (part == 1) g_K[idx] = v;
            else                g_V[idx] = v;
        }
    }
}

/* ------------------------------------------------------------------ */
/* Flash attention, fp32. One query row per thread, 128 rows per CTA.  */
/* grid = (SEQ/128, BATCH*HEADS)                                       */
/* ------------------------------------------------------------------ */
__global__ __launch_bounds__(128) void attn_kernel()
{
    __shared__ float Ks[32][64];
    __shared__ float Vs[32][64];

    const int bh  = blockIdx.y;                 /* 0..31 = b*16+h */
    const int tid = threadIdx.x;
    const int row = blockIdx.x * 128 + tid;     /* query index in [0,2048) */

    const float* Qp = g_Q + ((size_t)bh * SEQ + row) * HD;
    const float* Kb = g_K + (size_t)bh * SEQ * HD;
    const float* Vb = g_V + (size_t)bh * SEQ * HD;

    float4 q[16];
#pragma unroll
    for (int i = 0; i < 16; i++) q[i] = *(const float4*)(Qp + i*4);

    float o[64];
#pragma unroll
    for (int i = 0; i < 64; i++) o[i] = 0.f;
    float mi = -1e30f, li = 0.f;

    float sreg[32];   /* per-thread tile scores */

    for (int t = 0; t < SEQ; t += 32) {
        __syncthreads();
        /* cooperative K/V tile load: 32x64 each; 512 float4 per tile */
#pragma unroll
        for (int i = 0; i < 4; i++) {
            const int e = tid + i*128;           /* 0..511 */
            const int r = e >> 4;
            const int c = (e & 15) * 4;
            *(float4*)&Ks[r][c] = *(const float4*)(Kb + (size_t)(t + r)*64 + c);
            *(float4*)&Vs[r][c] = *(const float4*)(Vb + (size_t)(t + r)*64 + c);
        }
        __syncthreads();

        float mnew = mi;
#pragma unroll 4
        for (int j = 0; j < 32; j++) {
            float s0 = 0.f, s1 = 0.f, s2 = 0.f, s3 = 0.f;
#pragma unroll
            for (int dd = 0; dd < 16; dd++) {
                const float4 kv = *(const float4*)&Ks[j][dd*4];
                const float4 qv = q[dd];
                s0 = fmaf(qv.x, kv.x, s0);
                s1 = fmaf(qv.y, kv.y, s1);
                s2 = fmaf(qv.z, kv.z, s2);
                s3 = fmaf(qv.w, kv.w, s3);
            }
            const float s = (s0 + s1) + (s2 + s3);
            sreg[j] = s;
            mnew = fmaxf(mnew, s);
        }

        const float corr = exp2f((mi - mnew) * LOG2E);
        li *= corr;
#pragma unroll
        for (int i = 0; i < 64; i++) o[i] *= corr;

        float lad = 0.f;
#pragma unroll
        for (int j = 0; j < 32; j++) {
            const float p = exp2f((sreg[j] - mnew) * LOG2E);
            sreg[j] = p;
            lad += p;
        }
        li += lad;
        mi = mnew;

#pragma unroll 2
        for (int j = 0; j < 32; j++) {
            const float p = sreg[j];
#pragma unroll
            for (int dd = 0; dd < 16; dd++) {
                const float4 vv = *(const float4*)&Vs[j][dd*4];
                o[dd*4+0] = fmaf(p, vv.x, o[dd*4+0]);
                o[dd*4+1] = fmaf(p, vv.y, o[dd*4+1]);
                o[dd*4+2] = fmaf(p, vv.z, o[dd*4+2]);
                o[dd*4+3] = fmaf(p, vv.w, o[dd*4+3]);
            }
        }
    }

    const float inv = 1.f / li;
    const int b = bh >> 4, h = bh & 15;
    float* Apw = g_A + ((size_t)(b*SEQ + row))*EMBED + h*HD;
#pragma unroll
    for (int i = 0; i < 64; i += 4) {
        float4 v;
        v.x = o[i+0]*inv; v.y = o[i+1]*inv;
        v.z = o[i+2]*inv; v.w = o[i+3]*inv;
        *(float4*)(Apw + i) = v;
    }
}

/* ------------------------------------------------------------------ */
/* Projection GEMM: out[m,n] = sum_k A[m,k]*Wp[n,k] + bias[n]          */
/* M=4096, N=1024, K=1024                                              */
/* ------------------------------------------------------------------ */
__global__ __launch_bounds__(256) void proj_gemm(const float* __restrict__ Wp,
                                                 const float* __restrict__ bias,
                                                 float* __restrict__ out)
{
    __shared__ float As[8][128];
    __shared__ float Bs[8][128];

    const int bm = blockIdx.y * 128;
    const int bn = blockIdx.x * 128;
    const int tid = threadIdx.x;
    const int tr = tid >> 4;
    const int tc = tid & 15;
    const int lrow = tid >> 1;
    const int lk   = (tid & 1) * 4;

    const float* Ap = g_A + (size_t)(bm + lrow) * 1024 + lk;
    const float* Bp = Wp  + (size_t)(bn + lrow) * 1024 + lk;

    float acc[8][8];
#pragma unroll
    for (int i = 0; i < 8; i++)
#pragma unroll
        for (int j = 0; j < 8; j++) acc[i][j] = 0.f;

    for (int k0 = 0; k0 < 1024; k0 += 8) {
        float4 av = *(const float4*)(Ap + k0);
        float4 bv = *(const float4*)(Bp + k0);
        As[lk+0][lrow] = av.x; As[lk+1][lrow] = av.y;
        As[lk+2][lrow] = av.z; As[lk+3][lrow] = av.w;
        Bs[lk+0][lrow] = bv.x; Bs[lk+1][lrow] = bv.y;
        Bs[lk+2][lrow] = bv.z; Bs[lk+3][lrow] = bv.w;
        __syncthreads();

#pragma unroll
        for (int kk = 0; kk < 8; kk++) {
            float a[8], b[8];
#pragma unroll
            for (int i = 0; i < 8; i++) a[i] = As[kk][tr*8 + i];
#pragma unroll
            for (int j = 0; j < 8; j++) b[j] = Bs[kk][tc*8 + j];
#pragma unroll
            for (int i = 0; i < 8; i++)
#pragma unroll
                for (int j = 0; j < 8; j++)
                    acc[i][j] = fmaf(a[i], b[j], acc[i][j]);
        }
        __syncthreads();
    }

#pragma unroll
    for (int i = 0; i < 8; i++) {
        const int m = bm + tr*8 + i;
        float* orow = out + (size_t)m * 1024 + bn + tc*8;
#pragma unroll
        for (int j = 0; j < 8; j++)
            orow[j] = acc[i][j] + bias[bn + tc*8 + j];
    }
}

/* ------------------------------------------------------------------ */
extern "C" void kernel_launch(void* const* d_in, const int* in_sizes, int n_in,
                              void* d_out, int out_size)
{
    const float* x      = (const float*)d_in[0];
    /* d_in[1] = xpos (int32) — unused by the reference computation */
    const float* qkv_w  = (const float*)d_in[2];
    const float* proj_w = (const float*)d_in[3];
    const float* proj_b = (const float*)d_in[4];
    float* out = (float*)d_out;

    dim3 gq(NQKV/128, MROWS/128);   /* 24 x 32 */
    qkv_gemm<<<gq, 256>>>(x, qkv_w);

    dim3 ga(SEQ/128, BATCH*HEADS);  /* 16 x 32 */
    attn_kernel<<<ga, 128>>>();

    dim3 gp(EMBED/128, MROWS/128);  /* 8 x 32 */
    proj_gemm<<<gp, 256>>>(proj_w, proj_b, out);
}

// round 9
// speedup vs baseline: 1.3169x; 1.3169x over previous
#include <cuda_runtime.h>
#include <cuda_bf16.h>
#include <cstdint>
#include <math.h>

#define EMBED   1024
#define HEADS   16
#define HD      64
#define BATCH   2
#define SEQ     2048
#define MROWS   (BATCH*SEQ)       /* 4096 */
#define NQKV    (3*EMBED)         /* 3072 */
#define LOG2E   1.44269504088896f

/* ---------------- scratch (__device__ globals; no allocation allowed) -- */
__device__ float g_Q[BATCH*HEADS*SEQ*HD];
__device__ float g_K[BATCH*HEADS*SEQ*HD];
__device__ float g_V[BATCH*HEADS*SEQ*HD];
__device__ float g_A[BATCH*SEQ*EMBED];

__device__ __nv_bfloat16 g_Xh[MROWS*EMBED],  g_Xl[MROWS*EMBED];
__device__ __nv_bfloat16 g_Wh[NQKV*EMBED],   g_Wl[NQKV*EMBED];
__device__ __nv_bfloat16 g_Ph[EMBED*EMBED],  g_Pl[EMBED*EMBED];
__device__ __nv_bfloat16 g_Ah[MROWS*EMBED],  g_Al[MROWS*EMBED];

/* ---------------- helpers ---------------------------------------------- */
__device__ __forceinline__ uint32_t smem_u32(const void* p) {
    uint32_t a;
    asm("{ .reg .u64 t; cvta.to.shared.u64 t, %1; cvt.u32.u64 %0, t; }"
        : "=r"(a) : "l"(p));
    return a;
}
__device__ __forceinline__ void cp16(uint32_t dst, const void* src) {
    asm volatile("cp.async.cg.shared.global [%0], [%1], 16;" :: "r"(dst), "l"(src));
}
#define CP_COMMIT() asm volatile("cp.async.commit_group;" ::: "memory")
#define CP_WAIT(n)  asm volatile("cp.async.wait_group %0;" :: "n"(n) : "memory")

__device__ __forceinline__ void ldm_x4(uint32_t& r0, uint32_t& r1,
                                       uint32_t& r2, uint32_t& r3, uint32_t addr) {
    asm volatile("ldmatrix.sync.aligned.m8n8.x4.shared.b16 {%0,%1,%2,%3}, [%4];"
                 : "=r"(r0), "=r"(r1), "=r"(r2), "=r"(r3) : "r"(addr));
}
__device__ __forceinline__ void mma_bf16(float* c, const uint32_t* a,
                                         uint32_t b0, uint32_t b1) {
    asm volatile("mma.sync.aligned.m16n8k16.row.col.f32.bf16.bf16.f32 "
                 "{%0,%1,%2,%3}, {%4,%5,%6,%7}, {%8,%9}, {%0,%1,%2,%3};"
                 : "+f"(c[0]), "+f"(c[1]), "+f"(c[2]), "+f"(c[3])
                 : "r"(a[0]), "r"(a[1]), "r"(a[2]), "r"(a[3]), "r"(b0), "r"(b1));
}
/* swizzle for 32B-row tiles: flip bit4 by XOR of offset bits 5 and 7 */
__device__ __forceinline__ uint32_t swz(uint32_t o) {
    return o ^ ((((o >> 5) ^ (o >> 7)) & 1u) << 4);
}

/* ---------------- fp32 -> bf16 (hi, lo) conversion --------------------- */
/* DST 0..2: src comes from kernel arg (harness device pointers).          */
/* DST 3: src is the device global g_A — resolved IN DEVICE CODE (the R3- */
/* R7 bug was passing g_A from host, which ATS-reads the host shadow).    */
template<int DST>
__global__ __launch_bounds__(256) void conv_hl(const float* __restrict__ src_arg, int n4)
{
    const float* src = (DST == 3) ? (const float*)g_A : src_arg;
    __nv_bfloat16* hi = (DST==0) ? g_Xh : (DST==1) ? g_Wh : (DST==2) ? g_Ph : g_Ah;
    __nv_bfloat16* lo = (DST==0) ? g_Xl : (DST==1) ? g_Wl : (DST==2) ? g_Pl : g_Al;
    for (int i = blockIdx.x * 256 + threadIdx.x; i < n4; i += gridDim.x * 256) {
        float4 v = ((const float4*)src)[i];
        __nv_bfloat16 h0 = __float2bfloat16_rn(v.x);
        __nv_bfloat16 h1 = __float2bfloat16_rn(v.y);
        __nv_bfloat16 h2 = __float2bfloat16_rn(v.z);
        __nv_bfloat16 h3 = __float2bfloat16_rn(v.w);
        __nv_bfloat16 l0 = __float2bfloat16_rn(v.x - __bfloat162float(h0));
        __nv_bfloat16 l1 = __float2bfloat16_rn(v.y - __bfloat162float(h1));
        __nv_bfloat16 l2 = __float2bfloat16_rn(v.z - __bfloat162float(h2));
        __nv_bfloat16 l3 = __float2bfloat16_rn(v.w - __bfloat162float(h3));
        __nv_bfloat162 hp0; hp0.x = h0; hp0.y = h1;
        __nv_bfloat162 hp1; hp1.x = h2; hp1.y = h3;
        __nv_bfloat162 lp0; lp0.x = l0; lp0.y = l1;
        __nv_bfloat162 lp1; lp1.x = l2; lp1.y = l3;
        ((__nv_bfloat162*)hi)[i*2+0] = hp0;
        ((__nv_bfloat162*)hi)[i*2+1] = hp1;
        ((__nv_bfloat162*)lo)[i*2+0] = lp0;
        ((__nv_bfloat162*)lo)[i*2+1] = lp1;
    }
}

/* ---------------- warp-MMA bf16x3 GEMM ---------------------------------- */
/* C[m,n] = sum_k A[m,k]*B[n,k]; K=1024; BK=16 chunks, double-buffered.    */
/* 32KB dynamic smem -> no opt-in attribute needed.                        */
#define BK      16
#define NCH     (1024/BK)              /* 64 */
#define TILE_B  4096
#define STAGE_B (4*TILE_B)             /* 16KB */
#define GEMM_SMEM (2*STAGE_B)          /* 32KB */

template<int MODE>
__global__ __launch_bounds__(256) void gemm_mma(const float* __restrict__ bias,
                                                float* __restrict__ out)
{
    extern __shared__ char smem_raw[];
    const int tid = threadIdx.x, wid = tid >> 5, lane = tid & 31;
    const int bm = blockIdx.y * 128, bn = blockIdx.x * 128;

    const __nv_bfloat16* Ahp = (MODE == 0) ? g_Xh : g_Ah;
    const __nv_bfloat16* Alp = (MODE == 0) ? g_Xl : g_Al;
    const __nv_bfloat16* Bhp = (MODE == 0) ? g_Wh : g_Ph;
    const __nv_bfloat16* Blp = (MODE == 0) ? g_Wl : g_Pl;

    const uint32_t sbase = smem_u32(smem_raw);

    const int lr = tid >> 1;                 /* row 0..127 */
    const int lu = tid & 1;                  /* 16B unit    */
    const uint32_t so = swz((uint32_t)(lr * 32 + lu * 16));

    const int wm = (wid >> 2) * 64;
    const int wn = (wid & 3) * 32;

    const int a_r = wm + (lane & 15);
    const uint32_t a_off = swz((uint32_t)(a_r * 32 + (lane >> 4) * 16));
    const int b_r = wn + (lane & 7) + ((lane >> 4) << 3);
    const uint32_t b_off = swz((uint32_t)(b_r * 32 + ((lane >> 3) & 1) * 16));

    float acc[4][4][4];
#pragma unroll
    for (int mt = 0; mt < 4; mt++)
#pragma unroll
        for (int nt = 0; nt < 4; nt++)
#pragma unroll
            for (int i = 0; i < 4; i++) acc[mt][nt][i] = 0.f;

    auto load_chunk = [&](int stage, int k0) {
        const uint32_t sb = sbase + stage * STAGE_B;
        const size_t ga = (size_t)(bm + lr) * 1024 + k0 + lu * 8;
        const size_t gb = (size_t)(bn + lr) * 1024 + k0 + lu * 8;
        cp16(sb + so,            Ahp + ga);
        cp16(sb + TILE_B + so,   Alp + ga);
        cp16(sb + 2*TILE_B + so, Bhp + gb);
        cp16(sb + 3*TILE_B + so, Blp + gb);
    };

    load_chunk(0, 0);
    CP_COMMIT();

    for (int c = 0; c < NCH; c++) {
        if (c + 1 < NCH) {
            load_chunk((c + 1) & 1, (c + 1) * BK);
            CP_COMMIT();
            CP_WAIT(1);
        } else {
            CP_WAIT(0);
        }
        __syncthreads();

        const uint32_t sb = sbase + (c & 1) * STAGE_B;
        uint32_t ah[4][4], al[4][4], bh[2][4], bl[2][4];
#pragma unroll
        for (int mt = 0; mt < 4; mt++) {
            const uint32_t off = a_off + mt * (16 * 32);
            ldm_x4(ah[mt][0], ah[mt][1], ah[mt][2], ah[mt][3], sb + off);
            ldm_x4(al[mt][0], al[mt][1], al[mt][2], al[mt][3], sb + TILE_B + off);
        }
#pragma unroll
        for (int np = 0; np < 2; np++) {
            const uint32_t off = b_off + np * (16 * 32);
            ldm_x4(bh[np][0], bh[np][1], bh[np][2], bh[np][3], sb + 2*TILE_B + off);
            ldm_x4(bl[np][0], bl[np][1], bl[np][2], bl[np][3], sb + 3*TILE_B + off);
        }
#pragma unroll
        for (int mt = 0; mt < 4; mt++)
#pragma unroll
            for (int nt = 0; nt < 4; nt++) {
                const int np = nt >> 1, h = (nt & 1) * 2;
                mma_bf16(acc[mt][nt], ah[mt], bh[np][h], bh[np][h+1]);
                mma_bf16(acc[mt][nt], ah[mt], bl[np][h], bl[np][h+1]);
                mma_bf16(acc[mt][nt], al[mt], bh[np][h], bh[np][h+1]);
            }
        __syncthreads();
    }

    const int gr = lane >> 2, cp = (lane & 3) * 2;
#pragma unroll
    for (int mt = 0; mt < 4; mt++) {
        const int m0 = bm + wm + mt*16 + gr;
#pragma unroll
        for (int half = 0; half < 2; half++) {
            const int m = m0 + half * 8;
#pragma unroll
            for (int nt = 0; nt < 4; nt++) {
                const int n = bn + wn + nt*8 + cp;
                float2 v;
                v.x = acc[mt][nt][half*2 + 0];
                v.y = acc[mt][nt][half*2 + 1];
                if (MODE == 0) {
                    const int b = m >> 11, s = m & 2047;
                    const int part = n >> 10, hh = (n >> 6) & 15, dd = n & 63;
                    const size_t idx = (((size_t)(b*HEADS + hh))*SEQ + s)*HD + dd;
                    if (part == 0) {
                        v.x *= 0.125f; v.y *= 0.125f;
                        *(float2*)(g_Q + idx) = v;
                    } else if (part == 1) {
                        *(float2*)(g_K + idx) = v;
                    } else {
                        *(float2*)(g_V + idx) = v;
                    }
                } else {
                    v.x += bias[n]; v.y += bias[n+1];
                    *(float2*)(out + (size_t)m * 1024 + n) = v;
                }
            }
        }
    }
}

/* ---------------- flash attention, fp32 (proven in R1) ------------------ */
__global__ __launch_bounds__(128) void attn_kernel()
{
    __shared__ float Ks[32][64];
    __shared__ float Vs[32][64];

    const int bh  = blockIdx.y;
    const int tid = threadIdx.x;
    const int row = blockIdx.x * 128 + tid;

    const float* Qp = g_Q + ((size_t)bh * SEQ + row) * HD;
    const float* Kb = g_K + (size_t)bh * SEQ * HD;
    const float* Vb = g_V + (size_t)bh * SEQ * HD;

    float4 q[16];
#pragma unroll
    for (int i = 0; i < 16; i++) q[i] = *(const float4*)(Qp + i*4);

    float o[64];
#pragma unroll
    for (int i = 0; i < 64; i++) o[i] = 0.f;
    float mi = -1e30f, li = 0.f;
    float sreg[32];

    for (int t = 0; t < SEQ; t += 32) {
        __syncthreads();
#pragma unroll
        for (int i = 0; i < 4; i++) {
            const int e = tid + i*128;
            const int r = e >> 4;
            const int c = (e & 15) * 4;
            *(float4*)&Ks[r][c] = *(const float4*)(Kb + (size_t)(t + r)*64 + c);
            *(float4*)&Vs[r][c] = *(const float4*)(Vb + (size_t)(t + r)*64 + c);
        }
        __syncthreads();

        float mnew = mi;
#pragma unroll 4
        for (int j = 0; j < 32; j++) {
            float s0 = 0.f, s1 = 0.f, s2 = 0.f, s3 = 0.f;
#pragma unroll
            for (int dd = 0; dd < 16; dd++) {
                const float4 kv = *(const float4*)&Ks[j][dd*4];
                const float4 qv = q[dd];
                s0 = fmaf(qv.x, kv.x, s0);
                s1 = fmaf(qv.y, kv.y, s1);
                s2 = fmaf(qv.z, kv.z, s2);
                s3 = fmaf(qv.w, kv.w, s3);
            }
            const float s = (s0 + s1) + (s2 + s3);
            sreg[j] = s;
            mnew = fmaxf(mnew, s);
        }

        const float corr = exp2f((mi - mnew) * LOG2E);
        li *= corr;
#pragma unroll
        for (int i = 0; i < 64; i++) o[i] *= corr;

        float lad = 0.f;
#pragma unroll
        for (int j = 0; j < 32; j++) {
            const float p = exp2f((sreg[j] - mnew) * LOG2E);
            sreg[j] = p;
            lad += p;
        }
        li += lad;
        mi = mnew;

#pragma unroll 2
        for (int j = 0; j < 32; j++) {
            const float p = sreg[j];
#pragma unroll
            for (int dd = 0; dd < 16; dd++) {
                const float4 vv = *(const float4*)&Vs[j][dd*4];
                o[dd*4+0] = fmaf(p, vv.x, o[dd*4+0]);
                o[dd*4+1] = fmaf(p, vv.y, o[dd*4+1]);
                o[dd*4+2] = fmaf(p, vv.z, o[dd*4+2]);
                o[dd*4+3] = fmaf(p, vv.w, o[dd*4+3]);
            }
        }
    }

    const float inv = 1.f / li;
    const int b = bh >> 4, h = bh & 15;
    float* Apw = g_A + ((size_t)(b*SEQ + row))*EMBED + h*HD;
#pragma unroll
    for (int i = 0; i < 64; i += 4) {
        float4 v;
        v.x = o[i+0]*inv; v.y = o[i+1]*inv;
        v.z = o[i+2]*inv; v.w = o[i+3]*inv;
        *(float4*)(Apw + i) = v;
    }
}

/* ---------------- launch ------------------------------------------------ */
extern "C" void kernel_launch(void* const* d_in, const int* in_sizes, int n_in,
                              void* d_out, int out_size)
{
    const float* x      = (const float*)d_in[0];
    /* d_in[1] = xpos (unused) */
    const float* qkv_w  = (const float*)d_in[2];
    const float* proj_w = (const float*)d_in[3];
    const float* proj_b = (const float*)d_in[4];
    float* out = (float*)d_out;

    conv_hl<0><<<512, 256>>>(x,      MROWS*EMBED/4);
    conv_hl<1><<<512, 256>>>(qkv_w,  NQKV*EMBED/4);
    conv_hl<2><<<512, 256>>>(proj_w, EMBED*EMBED/4);

    dim3 gq(NQKV/128, MROWS/128);          /* 24 x 32 */
    gemm_mma<0><<<gq, 256, GEMM_SMEM>>>(nullptr, nullptr);

    dim3 ga(SEQ/128, BATCH*HEADS);         /* 16 x 32 */
    attn_kernel<<<ga, 128>>>();

    /* DST=3 reads g_A inside device code; host must NOT pass the symbol */
    conv_hl<3><<<512, 256>>>(nullptr, MROWS*EMBED/4);

    dim3 gp(EMBED/128, MROWS/128);         /* 8 x 32 */
    gemm_mma<1><<<gp, 256, GEMM_SMEM>>>(proj_b, out);
}

// round 11
// speedup vs baseline: 4.6234x; 3.5108x over previous
#include <cuda_runtime.h>
#include <cuda_bf16.h>
#include <cuda_fp16.h>
#include <cstdint>
#include <math.h>

#define EMBED   1024
#define HEADS   16
#define HD      64
#define BATCH   2
#define SEQ     2048
#define MROWS   (BATCH*SEQ)       /* 4096 */
#define NQKV    (3*EMBED)         /* 3072 */
#define LOG2E   1.44269504088896f

/* ---------------- scratch (__device__ globals) ------------------------- */
__device__ __half g_Qf[BATCH*HEADS*SEQ*HD];   /* pre-scaled by 0.125*log2e */
__device__ __half g_Kf[BATCH*HEADS*SEQ*HD];
__device__ __half g_Vf[BATCH*HEADS*SEQ*HD];

__device__ __nv_bfloat16 g_Xh[MROWS*EMBED],  g_Xl[MROWS*EMBED];
__device__ __nv_bfloat16 g_Wh[NQKV*EMBED],   g_Wl[NQKV*EMBED];
__device__ __nv_bfloat16 g_Ph[EMBED*EMBED],  g_Pl[EMBED*EMBED];
__device__ __nv_bfloat16 g_Ah[MROWS*EMBED],  g_Al[MROWS*EMBED];

/* ---------------- helpers ---------------------------------------------- */
__device__ __forceinline__ uint32_t smem_u32(const void* p) {
    uint32_t a;
    asm("{ .reg .u64 t; cvta.to.shared.u64 t, %1; cvt.u32.u64 %0, t; }"
        : "=r"(a) : "l"(p));
    return a;
}
__device__ __forceinline__ void cp16(uint32_t dst, const void* src) {
    asm volatile("cp.async.cg.shared.global [%0], [%1], 16;" :: "r"(dst), "l"(src));
}
#define CP_COMMIT() asm volatile("cp.async.commit_group;" ::: "memory")
#define CP_WAIT(n)  asm volatile("cp.async.wait_group %0;" :: "n"(n) : "memory")

__device__ __forceinline__ void ldm_x4(uint32_t& r0, uint32_t& r1,
                                       uint32_t& r2, uint32_t& r3, uint32_t addr) {
    asm volatile("ldmatrix.sync.aligned.m8n8.x4.shared.b16 {%0,%1,%2,%3}, [%4];"
                 : "=r"(r0), "=r"(r1), "=r"(r2), "=r"(r3) : "r"(addr));
}
__device__ __forceinline__ void ldm_x4_t(uint32_t& r0, uint32_t& r1,
                                         uint32_t& r2, uint32_t& r3, uint32_t addr) {
    asm volatile("ldmatrix.sync.aligned.m8n8.x4.trans.shared.b16 {%0,%1,%2,%3}, [%4];"
                 : "=r"(r0), "=r"(r1), "=r"(r2), "=r"(r3) : "r"(addr));
}
__device__ __forceinline__ void mma_bf16(float* c, const uint32_t* a,
                                         uint32_t b0, uint32_t b1) {
    asm volatile("mma.sync.aligned.m16n8k16.row.col.f32.bf16.bf16.f32 "
                 "{%0,%1,%2,%3}, {%4,%5,%6,%7}, {%8,%9}, {%0,%1,%2,%3};"
                 : "+f"(c[0]), "+f"(c[1]), "+f"(c[2]), "+f"(c[3])
                 : "r"(a[0]), "r"(a[1]), "r"(a[2]), "r"(a[3]), "r"(b0), "r"(b1));
}
__device__ __forceinline__ void mma_f16(float* c, const uint32_t* a,
                                        uint32_t b0, uint32_t b1) {
    asm volatile("mma.sync.aligned.m16n8k16.row.col.f32.f16.f16.f32 "
                 "{%0,%1,%2,%3}, {%4,%5,%6,%7}, {%8,%9}, {%0,%1,%2,%3};"
                 : "+f"(c[0]), "+f"(c[1]), "+f"(c[2]), "+f"(c[3])
                 : "r"(a[0]), "r"(a[1]), "r"(a[2]), "r"(a[3]), "r"(b0), "r"(b1));
}
/* 32B-row tile swizzle (GEMM path) */
__device__ __forceinline__ uint32_t swz(uint32_t o) {
    return o ^ ((((o >> 5) ^ (o >> 7)) & 1u) << 4);
}
/* 128B-row tile swizzle (attention K/V tiles) */
__device__ __forceinline__ uint32_t swz128(uint32_t o) {
    return o ^ ((o >> 3) & 0x70);
}

/* ---------------- fp32 -> bf16 (hi, lo) conversion --------------------- */
template<int DST>
__global__ __launch_bounds__(256) void conv_hl(const float* __restrict__ src, int n4)
{
    __nv_bfloat16* hi = (DST==0) ? g_Xh : (DST==1) ? g_Wh : g_Ph;
    __nv_bfloat16* lo = (DST==0) ? g_Xl : (DST==1) ? g_Wl : g_Pl;
    for (int i = blockIdx.x * 256 + threadIdx.x; i < n4; i += gridDim.x * 256) {
        float4 v = ((const float4*)src)[i];
        __nv_bfloat16 h0 = __float2bfloat16_rn(v.x);
        __nv_bfloat16 h1 = __float2bfloat16_rn(v.y);
        __nv_bfloat16 h2 = __float2bfloat16_rn(v.z);
        __nv_bfloat16 h3 = __float2bfloat16_rn(v.w);
        __nv_bfloat16 l0 = __float2bfloat16_rn(v.x - __bfloat162float(h0));
        __nv_bfloat16 l1 = __float2bfloat16_rn(v.y - __bfloat162float(h1));
        __nv_bfloat16 l2 = __float2bfloat16_rn(v.z - __bfloat162float(h2));
        __nv_bfloat16 l3 = __float2bfloat16_rn(v.w - __bfloat162float(h3));
        __nv_bfloat162 hp0; hp0.x = h0; hp0.y = h1;
        __nv_bfloat162 hp1; hp1.x = h2; hp1.y = h3;
        __nv_bfloat162 lp0; lp0.x = l0; lp0.y = l1;
        __nv_bfloat162 lp1; lp1.x = l2; lp1.y = l3;
        ((__nv_bfloat162*)hi)[i*2+0] = hp0;
        ((__nv_bfloat162*)hi)[i*2+1] = hp1;
        ((__nv_bfloat162*)lo)[i*2+0] = lp0;
        ((__nv_bfloat162*)lo)[i*2+1] = lp1;
    }
}

/* ---------------- warp-MMA bf16x3 GEMM (validated R9) ------------------- */
#define BK      16
#define NCH     (1024/BK)
#define TILE_B  4096
#define STAGE_B (4*TILE_B)
#define GEMM_SMEM (2*STAGE_B)          /* 32KB */

template<int MODE>
__global__ __launch_bounds__(256) void gemm_mma(const float* __restrict__ bias,
                                                float* __restrict__ out)
{
    extern __shared__ char smem_raw[];
    const int tid = threadIdx.x, wid = tid >> 5, lane = tid & 31;
    const int bm = blockIdx.y * 128, bn = blockIdx.x * 128;

    const __nv_bfloat16* Ahp = (MODE == 0) ? g_Xh : g_Ah;
    const __nv_bfloat16* Alp = (MODE == 0) ? g_Xl : g_Al;
    const __nv_bfloat16* Bhp = (MODE == 0) ? g_Wh : g_Ph;
    const __nv_bfloat16* Blp = (MODE == 0) ? g_Wl : g_Pl;

    const uint32_t sbase = smem_u32(smem_raw);

    const int lr = tid >> 1;
    const int lu = tid & 1;
    const uint32_t so = swz((uint32_t)(lr * 32 + lu * 16));

    const int wm = (wid >> 2) * 64;
    const int wn = (wid & 3) * 32;

    const int a_r = wm + (lane & 15);
    const uint32_t a_off = swz((uint32_t)(a_r * 32 + (lane >> 4) * 16));
    const int b_r = wn + (lane & 7) + ((lane >> 4) << 3);
    const uint32_t b_off = swz((uint32_t)(b_r * 32 + ((lane >> 3) & 1) * 16));

    float acc[4][4][4];
#pragma unroll
    for (int mt = 0; mt < 4; mt++)
#pragma unroll
        for (int nt = 0; nt < 4; nt++)
#pragma unroll
            for (int i = 0; i < 4; i++) acc[mt][nt][i] = 0.f;

    auto load_chunk = [&](int stage, int k0) {
        const uint32_t sb = sbase + stage * STAGE_B;
        const size_t ga = (size_t)(bm + lr) * 1024 + k0 + lu * 8;
        const size_t gb = (size_t)(bn + lr) * 1024 + k0 + lu * 8;
        cp16(sb + so,            Ahp + ga);
        cp16(sb + TILE_B + so,   Alp + ga);
        cp16(sb + 2*TILE_B + so, Bhp + gb);
        cp16(sb + 3*TILE_B + so, Blp + gb);
    };

    load_chunk(0, 0);
    CP_COMMIT();

    for (int c = 0; c < NCH; c++) {
        if (c + 1 < NCH) {
            load_chunk((c + 1) & 1, (c + 1) * BK);
            CP_COMMIT();
            CP_WAIT(1);
        } else {
            CP_WAIT(0);
        }
        __syncthreads();

        const uint32_t sb = sbase + (c & 1) * STAGE_B;
        uint32_t ah[4][4], al[4][4], bh[2][4], bl[2][4];
#pragma unroll
        for (int mt = 0; mt < 4; mt++) {
            const uint32_t off = a_off + mt * (16 * 32);
            ldm_x4(ah[mt][0], ah[mt][1], ah[mt][2], ah[mt][3], sb + off);
            ldm_x4(al[mt][0], al[mt][1], al[mt][2], al[mt][3], sb + TILE_B + off);
        }
#pragma unroll
        for (int np = 0; np < 2; np++) {
            const uint32_t off = b_off + np * (16 * 32);
            ldm_x4(bh[np][0], bh[np][1], bh[np][2], bh[np][3], sb + 2*TILE_B + off);
            ldm_x4(bl[np][0], bl[np][1], bl[np][2], bl[np][3], sb + 3*TILE_B + off);
        }
#pragma unroll
        for (int mt = 0; mt < 4; mt++)
#pragma unroll
            for (int nt = 0; nt < 4; nt++) {
                const int np = nt >> 1, h = (nt & 1) * 2;
                mma_bf16(acc[mt][nt], ah[mt], bh[np][h], bh[np][h+1]);
                mma_bf16(acc[mt][nt], ah[mt], bl[np][h], bl[np][h+1]);
                mma_bf16(acc[mt][nt], al[mt], bh[np][h], bh[np][h+1]);
            }
        __syncthreads();
    }

    const int gr = lane >> 2, cp = (lane & 3) * 2;
    const float QSCL = 0.125f * LOG2E;
#pragma unroll
    for (int mt = 0; mt < 4; mt++) {
        const int m0 = bm + wm + mt*16 + gr;
#pragma unroll
        for (int half = 0; half < 2; half++) {
            const int m = m0 + half * 8;
#pragma unroll
            for (int nt = 0; nt < 4; nt++) {
                const int n = bn + wn + nt*8 + cp;
                float2 v;
                v.x = acc[mt][nt][half*2 + 0];
                v.y = acc[mt][nt][half*2 + 1];
                if (MODE == 0) {
                    const int b = m >> 11, s = m & 2047;
                    const int part = n >> 10, hh = (n >> 6) & 15, dd = n & 63;
                    const size_t idx = (((size_t)(b*HEADS + hh))*SEQ + s)*HD + dd;
                    if (part == 0) {
                        *(__half2*)(g_Qf + idx) = __floats2half2_rn(v.x*QSCL, v.y*QSCL);
                    } else if (part == 1) {
                        *(__half2*)(g_Kf + idx) = __floats2half2_rn(v.x, v.y);
                    } else {
                        *(__half2*)(g_Vf + idx) = __floats2half2_rn(v.x, v.y);
                    }
                } else {
                    v.x += bias[n]; v.y += bias[n+1];
                    *(float2*)(out + (size_t)m * 1024 + n) = v;
                }
            }
        }
    }
}

/* ---------------- fp16 tensor-core flash attention ---------------------- */
/* grid (SEQ/128, 32), 256 threads. Warp w handles rows blk*128+w*16..+15. */
/* KV tiles of 64 keys, double-buffered cp.async.                          */
__global__ __launch_bounds__(256) void attn_tc()
{
    __shared__ char kvs[2][2][64*128];     /* [stage][K|V][64 rows x 128B] */

    const int tid = threadIdx.x, wid = tid >> 5, lane = tid & 31;
    const int g = lane >> 2, qd = lane & 3;
    const int bh = blockIdx.y;
    const int q0 = blockIdx.x * 128 + wid * 16;
    const size_t base = (size_t)bh * SEQ * HD;

    /* Q A-fragments, loaded once from gmem */
    uint32_t qa[4][4];
    {
        const __half* Qp = g_Qf + base;
        const int r0 = q0 + g, r1 = q0 + g + 8;
#pragma unroll
        for (int ks = 0; ks < 4; ks++) {
            qa[ks][0] = *(const uint32_t*)(Qp + (size_t)r0*64 + ks*16 + 2*qd);
            qa[ks][1] = *(const uint32_t*)(Qp + (size_t)r1*64 + ks*16 + 2*qd);
            qa[ks][2] = *(const uint32_t*)(Qp + (size_t)r0*64 + ks*16 + 8 + 2*qd);
            qa[ks][3] = *(const uint32_t*)(Qp + (size_t)r1*64 + ks*16 + 8 + 2*qd);
        }
    }

    float o[8][4];
#pragma unroll
    for (int j = 0; j < 8; j++)
#pragma unroll
        for (int i = 0; i < 4; i++) o[j][i] = 0.f;
    float m0 = -1e30f, m1 = -1e30f, l0 = 0.f, l1 = 0.f;

    auto load_kv = [&](int s, int t) {
        const __half* Kg = g_Kf + base + (size_t)t * 64 * 64;
        const __half* Vg = g_Vf + base + (size_t)t * 64 * 64;
        const uint32_t kb = smem_u32(&kvs[s][0][0]);
        const uint32_t vb = smem_u32(&kvs[s][1][0]);
#pragma unroll
        for (int i = 0; i < 2; i++) {
            const int idx = tid + i * 256;        /* 0..511 */
            const int r = idx >> 3, u = idx & 7;
            const uint32_t off = swz128((uint32_t)(r * 128 + u * 16));
            cp16(kb + off, Kg + r * 64 + u * 8);
            cp16(vb + off, Vg + r * 64 + u * 8);
        }
    };

    /* ldmatrix lane coords */
    const int krow_in = (lane & 7) + ((lane >> 4) << 3);     /* K: n-row   */
    const uint32_t kunit = ((lane >> 3) & 1) * 16;           /* K: k-16B   */
    const int vrow_in = (lane & 7) + (((lane >> 3) & 1) << 3); /* V: k-row */
    const uint32_t vunit = (lane >> 4) << 4;                 /* V: n-16B   */

    load_kv(0, 0);
    CP_COMMIT();

    for (int t = 0; t < SEQ/64; t++) {
        if (t + 1 < SEQ/64) {
            load_kv((t + 1) & 1, t + 1);
            CP_COMMIT();
            CP_WAIT(1);
        } else {
            CP_WAIT(0);
        }
        __syncthreads();

        const uint32_t kb = smem_u32(&kvs[t & 1][0][0]);
        const uint32_t vb = smem_u32(&kvs[t & 1][1][0]);

        /* ---- scores S = Q K^T (already in exp2 domain) ---- */
        float sc[8][4];
#pragma unroll
        for (int j = 0; j < 8; j++)
#pragma unroll
            for (int i = 0; i < 4; i++) sc[j][i] = 0.f;

#pragma unroll
        for (int ks = 0; ks < 4; ks++) {
#pragma unroll
            for (int nw = 0; nw < 4; nw++) {
                uint32_t b0, b1, b2, b3;
                const int row = nw * 16 + krow_in;
                const uint32_t addr = kb + swz128((uint32_t)(row*128 + ks*32) + kunit);
                ldm_x4(b0, b1, b2, b3, addr);
                mma_f16(sc[2*nw],   qa[ks], b0, b1);
                mma_f16(sc[2*nw+1], qa[ks], b2, b3);
            }
        }

        /* ---- online softmax ---- */
        float mx0 = m0, mx1 = m1;
#pragma unroll
        for (int j = 0; j < 8; j++) {
            mx0 = fmaxf(mx0, fmaxf(sc[j][0], sc[j][1]));
            mx1 = fmaxf(mx1, fmaxf(sc[j][2], sc[j][3]));
        }
        mx0 = fmaxf(mx0, __shfl_xor_sync(0xffffffffu, mx0, 1));
        mx0 = fmaxf(mx0, __shfl_xor_sync(0xffffffffu, mx0, 2));
        mx1 = fmaxf(mx1, __shfl_xor_sync(0xffffffffu, mx1, 1));
        mx1 = fmaxf(mx1, __shfl_xor_sync(0xffffffffu, mx1, 2));

        const float c0 = exp2f(m0 - mx0);
        const float c1 = exp2f(m1 - mx1);
        m0 = mx0; m1 = mx1;
        l0 *= c0;  l1 *= c1;
#pragma unroll
        for (int j = 0; j < 8; j++) {
            o[j][0] *= c0; o[j][1] *= c0;
            o[j][2] *= c1; o[j][3] *= c1;
        }

        uint32_t pa[4][4];
        float s0 = 0.f, s1 = 0.f;
#pragma unroll
        for (int j = 0; j < 8; j++) {
            const float p0 = exp2f(sc[j][0] - m0);
            const float p1 = exp2f(sc[j][1] - m0);
            const float p2 = exp2f(sc[j][2] - m1);
            const float p3 = exp2f(sc[j][3] - m1);
            s0 += p0 + p1;  s1 += p2 + p3;
            const __half2 h01 = __floats2half2_rn(p0, p1);
            const __half2 h23 = __floats2half2_rn(p2, p3);
            const int kt = j >> 1;
            if ((j & 1) == 0) {
                pa[kt][0] = *(const uint32_t*)&h01;
                pa[kt][1] = *(const uint32_t*)&h23;
            } else {
                pa[kt][2] = *(const uint32_t*)&h01;
                pa[kt][3] = *(const uint32_t*)&h23;
            }
        }
        l0 += s0; l1 += s1;

        /* ---- O += P V (V^T B-frags via ldmatrix.trans) ---- */
#pragma unroll
        for (int kt = 0; kt < 4; kt++) {
#pragma unroll
            for (int nf = 0; nf < 4; nf++) {
                uint32_t v0, v1, v2, v3;
                const int row = kt * 16 + vrow_in;
                const uint32_t addr = vb + swz128((uint32_t)(row*128 + nf*32) + vunit);
                ldm_x4_t(v0, v1, v2, v3, addr);
                mma_f16(o[2*nf],   pa[kt], v0, v1);
                mma_f16(o[2*nf+1], pa[kt], v2, v3);
            }
        }
        __syncthreads();
    }

    /* ---- epilogue: normalize, write bf16 hi/lo A ---- */
    l0 += __shfl_xor_sync(0xffffffffu, l0, 1);
    l0 += __shfl_xor_sync(0xffffffffu, l0, 2);
    l1 += __shfl_xor_sync(0xffffffffu, l1, 1);
    l1 += __shfl_xor_sync(0xffffffffu, l1, 2);
    const float inv0 = 1.f / l0, inv1 = 1.f / l1;

    const int b = bh >> 4, h = bh & 15;
    const int row0 = q0 + g, row1 = q0 + g + 8;
    __nv_bfloat16* Ah0 = g_Ah + ((size_t)(b*SEQ + row0))*EMBED + h*HD;
    __nv_bfloat16* Al0 = g_Al + ((size_t)(b*SEQ + row0))*EMBED + h*HD;
    __nv_bfloat16* Ah1 = g_Ah + ((size_t)(b*SEQ + row1))*EMBED + h*HD;
    __nv_bfloat16* Al1 = g_Al + ((size_t)(b*SEQ + row1))*EMBED + h*HD;
#pragma unroll
    for (int j = 0; j < 8; j++) {
        const int d = j*8 + 2*qd;
        float f0 = o[j][0]*inv0, f1 = o[j][1]*inv0;
        float f2 = o[j][2]*inv1, f3 = o[j][3]*inv1;
        __nv_bfloat162 h2a, l2a, h2b, l2b;
        h2a.x = __float2bfloat16_rn(f0);
        h2a.y = __float2bfloat16_rn(f1);
        l2a.x = __float2bfloat16_rn(f0 - __bfloat162float(h2a.x));
        l2a.y = __float2bfloat16_rn(f1 - __bfloat162float(h2a.y));
        h2b.x = __float2bfloat16_rn(f2);
        h2b.y = __float2bfloat16_rn(f3);
        l2b.x = __float2bfloat16_rn(f2 - __bfloat162float(h2b.x));
        l2b.y = __float2bfloat16_rn(f3 - __bfloat162float(h2b.y));
        *(__nv_bfloat162*)(Ah0 + d) = h2a;
        *(__nv_bfloat162*)(Al0 + d) = l2a;
        *(__nv_bfloat162*)(Ah1 + d) = h2b;
        *(__nv_bfloat162*)(Al1 + d) = l2b;
    }
}

/* ---------------- launch ------------------------------------------------ */
extern "C" void kernel_launch(void* const* d_in, const int* in_sizes, int n_in,
                              void* d_out, int out_size)
{
    const float* x      = (const float*)d_in[0];
    /* d_in[1] = xpos (unused) */
    const float* qkv_w  = (const float*)d_in[2];
    const float* proj_w = (const float*)d_in[3];
    const float* proj_b = (const float*)d_in[4];
    float* out = (float*)d_out;

    conv_hl<0><<<512, 256>>>(x,      MROWS*EMBED/4);
    conv_hl<1><<<512, 256>>>(qkv_w,  NQKV*EMBED/4);
    conv_hl<2><<<512, 256>>>(proj_w, EMBED*EMBED/4);

    dim3 gq(NQKV/128, MROWS/128);          /* 24 x 32 */
    gemm_mma<0><<<gq, 256, GEMM_SMEM>>>(nullptr, nullptr);

    dim3 ga(SEQ/128, BATCH*HEADS);         /* 16 x 32 */
    attn_tc<<<ga, 256>>>();

    dim3 gp(EMBED/128, MROWS/128);         /* 8 x 32 */
    gemm_mma<1><<<gp, 256, GEMM_SMEM>>>(proj_b, out);
}

// round 13
// speedup vs baseline: 6.6792x; 1.4446x over previous
#include <cuda_runtime.h>
#include <cuda_bf16.h>
#include <cuda_fp16.h>
#include <cstdint>
#include <math.h>

#define EMBED   1024
#define HEADS   16
#define HD      64
#define BATCH   2
#define SEQ     2048
#define MROWS   (BATCH*SEQ)       /* 4096 */
#define NQKV    (3*EMBED)         /* 3072 */
#define LOG2E   1.44269504088896f

/* ---------------- scratch (__device__ globals) ------------------------- */
__device__ __half g_Qf[BATCH*HEADS*SEQ*HD];   /* pre-scaled by 0.125*log2e */
__device__ __half g_Kf[BATCH*HEADS*SEQ*HD];
__device__ __half g_Vf[BATCH*HEADS*SEQ*HD];

__device__ __half g_Xf[MROWS*EMBED];          /* activations, single fp16  */
__device__ __half g_Af[MROWS*EMBED];          /* attention output, fp16    */
__device__ __half g_Wh[NQKV*EMBED],  g_Wl[NQKV*EMBED];   /* qkv_w hi/lo   */
__device__ __half g_Ph[EMBED*EMBED], g_Pl[EMBED*EMBED];  /* proj_w hi/lo  */

/* ---------------- helpers ---------------------------------------------- */
__device__ __forceinline__ uint32_t smem_u32(const void* p) {
    uint32_t a;
    asm("{ .reg .u64 t; cvta.to.shared.u64 t, %1; cvt.u32.u64 %0, t; }"
        : "=r"(a) : "l"(p));
    return a;
}
__device__ __forceinline__ void cp16(uint32_t dst, const void* src) {
    asm volatile("cp.async.cg.shared.global [%0], [%1], 16;" :: "r"(dst), "l"(src));
}
#define CP_COMMIT() asm volatile("cp.async.commit_group;" ::: "memory")
#define CP_WAIT(n)  asm volatile("cp.async.wait_group %0;" :: "n"(n) : "memory")

__device__ __forceinline__ void ldm_x4(uint32_t& r0, uint32_t& r1,
                                       uint32_t& r2, uint32_t& r3, uint32_t addr) {
    asm volatile("ldmatrix.sync.aligned.m8n8.x4.shared.b16 {%0,%1,%2,%3}, [%4];"
                 : "=r"(r0), "=r"(r1), "=r"(r2), "=r"(r3) : "r"(addr));
}
__device__ __forceinline__ void ldm_x4_t(uint32_t& r0, uint32_t& r1,
                                         uint32_t& r2, uint32_t& r3, uint32_t addr) {
    asm volatile("ldmatrix.sync.aligned.m8n8.x4.trans.shared.b16 {%0,%1,%2,%3}, [%4];"
                 : "=r"(r0), "=r"(r1), "=r"(r2), "=r"(r3) : "r"(addr));
}
__device__ __forceinline__ void mma_f16(float* c, const uint32_t* a,
                                        uint32_t b0, uint32_t b1) {
    asm volatile("mma.sync.aligned.m16n8k16.row.col.f32.f16.f16.f32 "
                 "{%0,%1,%2,%3}, {%4,%5,%6,%7}, {%8,%9}, {%0,%1,%2,%3};"
                 : "+f"(c[0]), "+f"(c[1]), "+f"(c[2]), "+f"(c[3])
                 : "r"(a[0]), "r"(a[1]), "r"(a[2]), "r"(a[3]), "r"(b0), "r"(b1));
}
/* 64B-row tile swizzle (GEMM tiles, BK=32) */
__device__ __forceinline__ uint32_t swz64(uint32_t o) {
    return o ^ ((o >> 3) & 0x30);
}
/* 128B-row tile swizzle (attention K/V tiles) */
__device__ __forceinline__ uint32_t swz128(uint32_t o) {
    return o ^ ((o >> 3) & 0x70);
}

/* ---------------- conversions ------------------------------------------ */
/* activations -> single fp16 */
__global__ __launch_bounds__(256) void conv_x(const float* __restrict__ src, int n4)
{
    for (int i = blockIdx.x * 256 + threadIdx.x; i < n4; i += gridDim.x * 256) {
        float4 v = ((const float4*)src)[i];
        ((__half2*)g_Xf)[i*2+0] = __floats2half2_rn(v.x, v.y);
        ((__half2*)g_Xf)[i*2+1] = __floats2half2_rn(v.z, v.w);
    }
}
/* weights -> fp16 (hi, lo); DST 0 = qkv_w, 1 = proj_w */
template<int DST>
__global__ __launch_bounds__(256) void conv_w(const float* __restrict__ src, int n4)
{
    __half* hi = (DST==0) ? g_Wh : g_Ph;
    __half* lo = (DST==0) ? g_Wl : g_Pl;
    for (int i = blockIdx.x * 256 + threadIdx.x; i < n4; i += gridDim.x * 256) {
        float4 v = ((const float4*)src)[i];
        __half h0 = __float2half_rn(v.x);
        __half h1 = __float2half_rn(v.y);
        __half h2 = __float2half_rn(v.z);
        __half h3 = __float2half_rn(v.w);
        __half l0 = __float2half_rn(v.x - __half2float(h0));
        __half l1 = __float2half_rn(v.y - __half2float(h1));
        __half l2 = __float2half_rn(v.z - __half2float(h2));
        __half l3 = __float2half_rn(v.w - __half2float(h3));
        __half2 hp0; hp0.x = h0; hp0.y = h1;
        __half2 hp1; hp1.x = h2; hp1.y = h3;
        __half2 lp0; lp0.x = l0; lp0.y = l1;
        __half2 lp1; lp1.x = l2; lp1.y = l3;
        ((__half2*)hi)[i*2+0] = hp0;
        ((__half2*)hi)[i*2+1] = hp1;
        ((__half2*)lo)[i*2+0] = lp0;
        ((__half2*)lo)[i*2+1] = lp1;
    }
}

/* ---------------- warp-MMA fp16 split-weight GEMM ----------------------- */
/* C[m,n] = sum_k A[m,k]*(Wh[n,k]+Wl[n,k]); K=1024; BK=32, double-buffer.  */
/* SMEM/stage: A (8KB) + Bh (8KB) + Bl (8KB) = 24KB; x2 = 48KB (no opt-in)*/
#define BK      32
#define NCH     (1024/BK)              /* 32 */
#define TILE_B  8192
#define STAGE_B (3*TILE_B)             /* 24KB */
#define GEMM_SMEM (2*STAGE_B)          /* 49152 */

template<int MODE>
__global__ __launch_bounds__(256) void gemm_mma(const float* __restrict__ bias,
                                                float* __restrict__ out)
{
    extern __shared__ char smem_raw[];
    const int tid = threadIdx.x, wid = tid >> 5, lane = tid & 31;
    const int bm = blockIdx.y * 128, bn = blockIdx.x * 128;

    const __half* Ap  = (MODE == 0) ? g_Xf : g_Af;
    const __half* Bhp = (MODE == 0) ? g_Wh : g_Ph;
    const __half* Blp = (MODE == 0) ? g_Wl : g_Pl;

    const uint32_t sbase = smem_u32(smem_raw);

    /* load coords: 512 16B-units per tile; threads cover 2 each */
    const int lr0 = tid >> 2;               /* rows 0..63  (i=0)  */
    const int lu  = tid & 3;                /* 16B unit 0..3      */

    const int wm = (wid >> 2) * 64;
    const int wn = (wid & 3) * 32;

    const int a_r = wm + (lane & 15);
    const int b_r = wn + (lane & 7) + ((lane >> 4) << 3);
    const uint32_t a_base = (uint32_t)(a_r * 64 + ((lane >> 4) << 4));
    const uint32_t b_base = (uint32_t)(b_r * 64 + (((lane >> 3) & 1) << 4));

    float acc[4][4][4];
#pragma unroll
    for (int mt = 0; mt < 4; mt++)
#pragma unroll
        for (int nt = 0; nt < 4; nt++)
#pragma unroll
            for (int i = 0; i < 4; i++) acc[mt][nt][i] = 0.f;

    auto load_chunk = [&](int stage, int k0) {
        const uint32_t sb = sbase + stage * STAGE_B;
#pragma unroll
        for (int i = 0; i < 2; i++) {
            const int r = lr0 + i * 64;
            const uint32_t so = swz64((uint32_t)(r * 64 + lu * 16));
            const size_t ga = (size_t)(bm + r) * 1024 + k0 + lu * 8;
            const size_t gb = (size_t)(bn + r) * 1024 + k0 + lu * 8;
            cp16(sb + so,            Ap  + ga);
            cp16(sb + TILE_B + so,   Bhp + gb);
            cp16(sb + 2*TILE_B + so, Blp + gb);
        }
    };

    load_chunk(0, 0);
    CP_COMMIT();

    for (int c = 0; c < NCH; c++) {
        if (c + 1 < NCH) {
            load_chunk((c + 1) & 1, (c + 1) * BK);
            CP_COMMIT();
            CP_WAIT(1);
        } else {
            CP_WAIT(0);
        }
        __syncthreads();

        const uint32_t sb = sbase + (c & 1) * STAGE_B;
#pragma unroll
        for (int ks = 0; ks < 2; ks++) {
            uint32_t ah[4][4], bh[2][4], bl[2][4];
#pragma unroll
            for (int mt = 0; mt < 4; mt++) {
                const uint32_t off = swz64(a_base + (uint32_t)(mt*16*64 + ks*32));
                ldm_x4(ah[mt][0], ah[mt][1], ah[mt][2], ah[mt][3], sb + off);
            }
#pragma unroll
            for (int np = 0; np < 2; np++) {
                const uint32_t off = swz64(b_base + (uint32_t)(np*16*64 + ks*32));
                ldm_x4(bh[np][0], bh[np][1], bh[np][2], bh[np][3], sb + TILE_B + off);
                ldm_x4(bl[np][0], bl[np][1], bl[np][2], bl[np][3], sb + 2*TILE_B + off);
            }
#pragma unroll
            for (int mt = 0; mt < 4; mt++)
#pragma unroll
                for (int nt = 0; nt < 4; nt++) {
                    const int np = nt >> 1, h = (nt & 1) * 2;
                    mma_f16(acc[mt][nt], ah[mt], bh[np][h], bh[np][h+1]);
                    mma_f16(acc[mt][nt], ah[mt], bl[np][h], bl[np][h+1]);
                }
        }
        __syncthreads();
    }

    const int gr = lane >> 2, cp = (lane & 3) * 2;
    const float QSCL = 0.125f * LOG2E;
#pragma unroll
    for (int mt = 0; mt < 4; mt++) {
        const int m0 = bm + wm + mt*16 + gr;
#pragma unroll
        for (int half = 0; half < 2; half++) {
            const int m = m0 + half * 8;
#pragma unroll
            for (int nt = 0; nt < 4; nt++) {
                const int n = bn + wn + nt*8 + cp;
                float2 v;
                v.x = acc[mt][nt][half*2 + 0];
                v.y = acc[mt][nt][half*2 + 1];
                if (MODE == 0) {
                    const int b = m >> 11, s = m & 2047;
                    const int part = n >> 10, hh = (n >> 6) & 15, dd = n & 63;
                    const size_t idx = (((size_t)(b*HEADS + hh))*SEQ + s)*HD + dd;
                    if (part == 0) {
                        *(__half2*)(g_Qf + idx) = __floats2half2_rn(v.x*QSCL, v.y*QSCL);
                    } else if (part == 1) {
                        *(__half2*)(g_Kf + idx) = __floats2half2_rn(v.x, v.y);
                    } else {
                        *(__half2*)(g_Vf + idx) = __floats2half2_rn(v.x, v.y);
                    }
                } else {
                    v.x += bias[n]; v.y += bias[n+1];
                    *(float2*)(out + (size_t)m * 1024 + n) = v;
                }
            }
        }
    }
}

/* ---------------- fp16 tensor-core flash attention (validated R11) ------ */
__global__ __launch_bounds__(256) void attn_tc()
{
    __shared__ char kvs[2][2][64*128];     /* [stage][K|V][64 rows x 128B] */

    const int tid = threadIdx.x, wid = tid >> 5, lane = tid & 31;
    const int g = lane >> 2, qd = lane & 3;
    const int bh = blockIdx.y;
    const int q0 = blockIdx.x * 128 + wid * 16;
    const size_t base = (size_t)bh * SEQ * HD;

    uint32_t qa[4][4];
    {
        const __half* Qp = g_Qf + base;
        const int r0 = q0 + g, r1 = q0 + g + 8;
#pragma unroll
        for (int ks = 0; ks < 4; ks++) {
            qa[ks][0] = *(const uint32_t*)(Qp + (size_t)r0*64 + ks*16 + 2*qd);
            qa[ks][1] = *(const uint32_t*)(Qp + (size_t)r1*64 + ks*16 + 2*qd);
            qa[ks][2] = *(const uint32_t*)(Qp + (size_t)r0*64 + ks*16 + 8 + 2*qd);
            qa[ks][3] = *(const uint32_t*)(Qp + (size_t)r1*64 + ks*16 + 8 + 2*qd);
        }
    }

    float o[8][4];
#pragma unroll
    for (int j = 0; j < 8; j++)
#pragma unroll
        for (int i = 0; i < 4; i++) o[j][i] = 0.f;
    float m0 = -1e30f, m1 = -1e30f, l0 = 0.f, l1 = 0.f;

    auto load_kv = [&](int s, int t) {
        const __half* Kg = g_Kf + base + (size_t)t * 64 * 64;
        const __half* Vg = g_Vf + base + (size_t)t * 64 * 64;
        const uint32_t kb = smem_u32(&kvs[s][0][0]);
        const uint32_t vb = smem_u32(&kvs[s][1][0]);
#pragma unroll
        for (int i = 0; i < 2; i++) {
            const int idx = tid + i * 256;
            const int r = idx >> 3, u = idx & 7;
            const uint32_t off = swz128((uint32_t)(r * 128 + u * 16));
            cp16(kb + off, Kg + r * 64 + u * 8);
            cp16(vb + off, Vg + r * 64 + u * 8);
        }
    };

    const int krow_in = (lane & 7) + ((lane >> 4) << 3);
    const uint32_t kunit = ((lane >> 3) & 1) * 16;
    const int vrow_in = (lane & 7) + (((lane >> 3) & 1) << 3);
    const uint32_t vunit = (lane >> 4) << 4;

    load_kv(0, 0);
    CP_COMMIT();

    for (int t = 0; t < SEQ/64; t++) {
        if (t + 1 < SEQ/64) {
            load_kv((t + 1) & 1, t + 1);
            CP_COMMIT();
            CP_WAIT(1);
        } else {
            CP_WAIT(0);
        }
        __syncthreads();

        const uint32_t kb = smem_u32(&kvs[t & 1][0][0]);
        const uint32_t vb = smem_u32(&kvs[t & 1][1][0]);

        float sc[8][4];
#pragma unroll
        for (int j = 0; j < 8; j++)
#pragma unroll
            for (int i = 0; i < 4; i++) sc[j][i] = 0.f;

#pragma unroll
        for (int ks = 0; ks < 4; ks++) {
#pragma unroll
            for (int nw = 0; nw < 4; nw++) {
                uint32_t b0, b1, b2, b3;
                const int row = nw * 16 + krow_in;
                const uint32_t addr = kb + swz128((uint32_t)(row*128 + ks*32) + kunit);
                ldm_x4(b0, b1, b2, b3, addr);
                mma_f16(sc[2*nw],   qa[ks], b0, b1);
                mma_f16(sc[2*nw+1], qa[ks], b2, b3);
            }
        }

        float mx0 = m0, mx1 = m1;
#pragma unroll
        for (int j = 0; j < 8; j++) {
            mx0 = fmaxf(mx0, fmaxf(sc[j][0], sc[j][1]));
            mx1 = fmaxf(mx1, fmaxf(sc[j][2], sc[j][3]));
        }
        mx0 = fmaxf(mx0, __shfl_xor_sync(0xffffffffu, mx0, 1));
        mx0 = fmaxf(mx0, __shfl_xor_sync(0xffffffffu, mx0, 2));
        mx1 = fmaxf(mx1, __shfl_xor_sync(0xffffffffu, mx1, 1));
        mx1 = fmaxf(mx1, __shfl_xor_sync(0xffffffffu, mx1, 2));

        const float c0 = exp2f(m0 - mx0);
        const float c1 = exp2f(m1 - mx1);
        m0 = mx0; m1 = mx1;
        l0 *= c0;  l1 *= c1;
#pragma unroll
        for (int j = 0; j < 8; j++) {
            o[j][0] *= c0; o[j][1] *= c0;
            o[j][2] *= c1; o[j][3] *= c1;
        }

        uint32_t pa[4][4];
        float s0 = 0.f, s1 = 0.f;
#pragma unroll
        for (int j = 0; j < 8; j++) {
            const float p0 = exp2f(sc[j][0] - m0);
            const float p1 = exp2f(sc[j][1] - m0);
            const float p2 = exp2f(sc[j][2] - m1);
            const float p3 = exp2f(sc[j][3] - m1);
            s0 += p0 + p1;  s1 += p2 + p3;
            const __half2 h01 = __floats2half2_rn(p0, p1);
            const __half2 h23 = __floats2half2_rn(p2, p3);
            const int kt = j >> 1;
            if ((j & 1) == 0) {
                pa[kt][0] = *(const uint32_t*)&h01;
                pa[kt][1] = *(const uint32_t*)&h23;
            } else {
                pa[kt][2] = *(const uint32_t*)&h01;
                pa[kt][3] = *(const uint32_t*)&h23;
            }
        }
        l0 += s0; l1 += s1;

#pragma unroll
        for (int kt = 0; kt < 4; kt++) {
#pragma unroll
            for (int nf = 0; nf < 4; nf++) {
                uint32_t v0, v1, v2, v3;
                const int row = kt * 16 + vrow_in;
                const uint32_t addr = vb + swz128((uint32_t)(row*128 + nf*32) + vunit);
                ldm_x4_t(v0, v1, v2, v3, addr);
                mma_f16(o[2*nf],   pa[kt], v0, v1);
                mma_f16(o[2*nf+1], pa[kt], v2, v3);
            }
        }
        __syncthreads();
    }

    l0 += __shfl_xor_sync(0xffffffffu, l0, 1);
    l0 += __shfl_xor_sync(0xffffffffu, l0, 2);
    l1 += __shfl_xor_sync(0xffffffffu, l1, 1);
    l1 += __shfl_xor_sync(0xffffffffu, l1, 2);
    const float inv0 = 1.f / l0, inv1 = 1.f / l1;

    const int b = bh >> 4, h = bh & 15;
    const int row0 = q0 + g, row1 = q0 + g + 8;
    __half* A0 = g_Af + ((size_t)(b*SEQ + row0))*EMBED + h*HD;
    __half* A1 = g_Af + ((size_t)(b*SEQ + row1))*EMBED + h*HD;
#pragma unroll
    for (int j = 0; j < 8; j++) {
        const int d = j*8 + 2*qd;
        *(__half2*)(A0 + d) = __floats2half2_rn(o[j][0]*inv0, o[j][1]*inv0);
        *(__half2*)(A1 + d) = __floats2half2_rn(o[j][2]*inv1, o[j][3]*inv1);
    }
}

/* ---------------- launch ------------------------------------------------ */
extern "C" void kernel_launch(void* const* d_in, const int* in_sizes, int n_in,
                              void* d_out, int out_size)
{
    const float* x      = (const float*)d_in[0];
    /* d_in[1] = xpos (unused) */
    const float* qkv_w  = (const float*)d_in[2];
    const float* proj_w = (const float*)d_in[3];
    const float* proj_b = (const float*)d_in[4];
    float* out = (float*)d_out;

    conv_x<<<512, 256>>>(x, MROWS*EMBED/4);
    conv_w<0><<<512, 256>>>(qkv_w,  NQKV*EMBED/4);
    conv_w<1><<<512, 256>>>(proj_w, EMBED*EMBED/4);

    dim3 gq(NQKV/128, MROWS/128);          /* 24 x 32 */
    gemm_mma<0><<<gq, 256, GEMM_SMEM>>>(nullptr, nullptr);

    dim3 ga(SEQ/128, BATCH*HEADS);         /* 16 x 32 */
    attn_tc<<<ga, 256>>>();

    dim3 gp(EMBED/128, MROWS/128);         /* 8 x 32 */
    gemm_mma<1><<<gp, 256, GEMM_SMEM>>>(proj_b, out);
}

// round 14
// speedup vs baseline: 8.5083x; 1.2739x over previous
#include <cuda_runtime.h>
#include <cuda_bf16.h>
#include <cuda_fp16.h>
#include <cstdint>
#include <math.h>

#define EMBED   1024
#define HEADS   16
#define HD      64
#define BATCH   2
#define SEQ     2048
#define MROWS   (BATCH*SEQ)       /* 4096 */
#define NQKV    (3*EMBED)         /* 3072 */
#define LOG2E   1.44269504088896f

/* ---------------- scratch (__device__ globals) ------------------------- */
__device__ __half g_Qf[BATCH*HEADS*SEQ*HD];   /* pre-scaled by 0.125*log2e */
__device__ __half g_Kf[BATCH*HEADS*SEQ*HD];
__device__ __half g_Vf[BATCH*HEADS*SEQ*HD];

__device__ __half g_Xf[MROWS*EMBED];          /* activations, single fp16  */
__device__ __half g_Af[MROWS*EMBED];          /* attention output, fp16    */
__device__ __half g_Wh[NQKV*EMBED];                      /* qkv_w, single */
__device__ __half g_Ph[EMBED*EMBED], g_Pl[EMBED*EMBED];  /* proj_w hi/lo  */

/* ---------------- helpers ---------------------------------------------- */
__device__ __forceinline__ uint32_t smem_u32(const void* p) {
    uint32_t a;
    asm("{ .reg .u64 t; cvta.to.shared.u64 t, %1; cvt.u32.u64 %0, t; }"
        : "=r"(a) : "l"(p));
    return a;
}
__device__ __forceinline__ void cp16(uint32_t dst, const void* src) {
    asm volatile("cp.async.cg.shared.global [%0], [%1], 16;" :: "r"(dst), "l"(src));
}
#define CP_COMMIT() asm volatile("cp.async.commit_group;" ::: "memory")
#define CP_WAIT(n)  asm volatile("cp.async.wait_group %0;" :: "n"(n) : "memory")

__device__ __forceinline__ void ldm_x4(uint32_t& r0, uint32_t& r1,
                                       uint32_t& r2, uint32_t& r3, uint32_t addr) {
    asm volatile("ldmatrix.sync.aligned.m8n8.x4.shared.b16 {%0,%1,%2,%3}, [%4];"
                 : "=r"(r0), "=r"(r1), "=r"(r2), "=r"(r3) : "r"(addr));
}
__device__ __forceinline__ void ldm_x4_t(uint32_t& r0, uint32_t& r1,
                                         uint32_t& r2, uint32_t& r3, uint32_t addr) {
    asm volatile("ldmatrix.sync.aligned.m8n8.x4.trans.shared.b16 {%0,%1,%2,%3}, [%4];"
                 : "=r"(r0), "=r"(r1), "=r"(r2), "=r"(r3) : "r"(addr));
}
__device__ __forceinline__ void mma_f16(float* c, const uint32_t* a,
                                        uint32_t b0, uint32_t b1) {
    asm volatile("mma.sync.aligned.m16n8k16.row.col.f32.f16.f16.f32 "
                 "{%0,%1,%2,%3}, {%4,%5,%6,%7}, {%8,%9}, {%0,%1,%2,%3};"
                 : "+f"(c[0]), "+f"(c[1]), "+f"(c[2]), "+f"(c[3])
                 : "r"(a[0]), "r"(a[1]), "r"(a[2]), "r"(a[3]), "r"(b0), "r"(b1));
}
__device__ __forceinline__ uint32_t swz64(uint32_t o)  { return o ^ ((o >> 3) & 0x30); }
__device__ __forceinline__ uint32_t swz128(uint32_t o) { return o ^ ((o >> 3) & 0x70); }

/* ---------------- fused conversion kernel ------------------------------- */
/* range [0,NX): x -> g_Xf (fp16)                                           */
/* range [NX,NX+NW): qkv_w -> g_Wh (fp16 single)                            */
/* range [NX+NW,NX+NW+NP): proj_w -> g_Ph/g_Pl (fp16 hi/lo)                 */
#define NX (MROWS*EMBED/4)
#define NW (NQKV*EMBED/4)
#define NP (EMBED*EMBED/4)
__global__ __launch_bounds__(256) void conv_all(const float* __restrict__ x,
                                                const float* __restrict__ qkv_w,
                                                const float* __restrict__ proj_w)
{
    for (int i = blockIdx.x * 256 + threadIdx.x; i < NX + NW + NP;
         i += gridDim.x * 256) {
        if (i < NX) {
            float4 v = ((const float4*)x)[i];
            ((__half2*)g_Xf)[i*2+0] = __floats2half2_rn(v.x, v.y);
            ((__half2*)g_Xf)[i*2+1] = __floats2half2_rn(v.z, v.w);
        } else if (i < NX + NW) {
            const int j = i - NX;
            float4 v = ((const float4*)qkv_w)[j];
            ((__half2*)g_Wh)[j*2+0] = __floats2half2_rn(v.x, v.y);
            ((__half2*)g_Wh)[j*2+1] = __floats2half2_rn(v.z, v.w);
        } else {
            const int j = i - NX - NW;
            float4 v = ((const float4*)proj_w)[j];
            __half h0 = __float2half_rn(v.x);
            __half h1 = __float2half_rn(v.y);
            __half h2 = __float2half_rn(v.z);
            __half h3 = __float2half_rn(v.w);
            __half l0 = __float2half_rn(v.x - __half2float(h0));
            __half l1 = __float2half_rn(v.y - __half2float(h1));
            __half l2 = __float2half_rn(v.z - __half2float(h2));
            __half l3 = __float2half_rn(v.w - __half2float(h3));
            __half2 hp0; hp0.x = h0; hp0.y = h1;
            __half2 hp1; hp1.x = h2; hp1.y = h3;
            __half2 lp0; lp0.x = l0; lp0.y = l1;
            __half2 lp1; lp1.x = l2; lp1.y = l3;
            ((__half2*)g_Ph)[j*2+0] = hp0;
            ((__half2*)g_Ph)[j*2+1] = hp1;
            ((__half2*)g_Pl)[j*2+0] = lp0;
            ((__half2*)g_Pl)[j*2+1] = lp1;
        }
    }
}

/* ---------------- warp-MMA fp16 GEMM ------------------------------------ */
/* MODE 0 (QKV): single-fp16 weights, 2 tiles/stage (A,Bh) = 16KB.         */
/* MODE 1 (proj): split weights, 3 tiles/stage (A,Bh,Bl) = 24KB.           */
#define BK      32
#define NCHG    (1024/BK)              /* 32 */
#define TILE_B  8192

template<int MODE>
__global__ __launch_bounds__(256) void gemm_mma(const float* __restrict__ bias,
                                                float* __restrict__ out)
{
    constexpr int NT = (MODE == 0) ? 2 : 3;          /* tiles per stage */
    constexpr int STAGE = NT * TILE_B;
    extern __shared__ char smem_raw[];
    const int tid = threadIdx.x, wid = tid >> 5, lane = tid & 31;
    const int bm = blockIdx.y * 128, bn = blockIdx.x * 128;

    const __half* Ap  = (MODE == 0) ? g_Xf : g_Af;
    const __half* Bhp = (MODE == 0) ? g_Wh : g_Ph;
    const __half* Blp = g_Pl;                        /* MODE 1 only */

    const uint32_t sbase = smem_u32(smem_raw);

    const int lr0 = tid >> 2;               /* rows 0..63  (i=0)  */
    const int lu  = tid & 3;                /* 16B unit 0..3      */

    const int wm = (wid >> 2) * 64;
    const int wn = (wid & 3) * 32;

    const int a_r = wm + (lane & 15);
    const int b_r = wn + (lane & 7) + ((lane >> 4) << 3);
    const uint32_t a_base = (uint32_t)(a_r * 64 + ((lane >> 4) << 4));
    const uint32_t b_base = (uint32_t)(b_r * 64 + (((lane >> 3) & 1) << 4));

    float acc[4][4][4];
#pragma unroll
    for (int mt = 0; mt < 4; mt++)
#pragma unroll
        for (int nt = 0; nt < 4; nt++)
#pragma unroll
            for (int i = 0; i < 4; i++) acc[mt][nt][i] = 0.f;

    auto load_chunk = [&](int stage, int k0) {
        const uint32_t sb = sbase + stage * STAGE;
#pragma unroll
        for (int i = 0; i < 2; i++) {
            const int r = lr0 + i * 64;
            const uint32_t so = swz64((uint32_t)(r * 64 + lu * 16));
            const size_t ga = (size_t)(bm + r) * 1024 + k0 + lu * 8;
            const size_t gb = (size_t)(bn + r) * 1024 + k0 + lu * 8;
            cp16(sb + so,          Ap  + ga);
            cp16(sb + TILE_B + so, Bhp + gb);
            if (MODE == 1) cp16(sb + 2*TILE_B + so, Blp + gb);
        }
    };

    load_chunk(0, 0);
    CP_COMMIT();

    for (int c = 0; c < NCHG; c++) {
        if (c + 1 < NCHG) {
            load_chunk((c + 1) & 1, (c + 1) * BK);
            CP_COMMIT();
            CP_WAIT(1);
        } else {
            CP_WAIT(0);
        }
        __syncthreads();

        const uint32_t sb = sbase + (c & 1) * STAGE;
#pragma unroll
        for (int ks = 0; ks < 2; ks++) {
            uint32_t ah[4][4], bh[2][4], bl[2][4];
#pragma unroll
            for (int mt = 0; mt < 4; mt++) {
                const uint32_t off = swz64(a_base + (uint32_t)(mt*16*64 + ks*32));
                ldm_x4(ah[mt][0], ah[mt][1], ah[mt][2], ah[mt][3], sb + off);
            }
#pragma unroll
            for (int np = 0; np < 2; np++) {
                const uint32_t off = swz64(b_base + (uint32_t)(np*16*64 + ks*32));
                ldm_x4(bh[np][0], bh[np][1], bh[np][2], bh[np][3], sb + TILE_B + off);
                if (MODE == 1)
                    ldm_x4(bl[np][0], bl[np][1], bl[np][2], bl[np][3], sb + 2*TILE_B + off);
            }
#pragma unroll
            for (int mt = 0; mt < 4; mt++)
#pragma unroll
                for (int nt = 0; nt < 4; nt++) {
                    const int np = nt >> 1, h = (nt & 1) * 2;
                    mma_f16(acc[mt][nt], ah[mt], bh[np][h], bh[np][h+1]);
                    if (MODE == 1)
                        mma_f16(acc[mt][nt], ah[mt], bl[np][h], bl[np][h+1]);
                }
        }
        __syncthreads();
    }

    const int gr = lane >> 2, cp = (lane & 3) * 2;
    const float QSCL = 0.125f * LOG2E;
#pragma unroll
    for (int mt = 0; mt < 4; mt++) {
        const int m0 = bm + wm + mt*16 + gr;
#pragma unroll
        for (int half = 0; half < 2; half++) {
            const int m = m0 + half * 8;
#pragma unroll
            for (int nt = 0; nt < 4; nt++) {
                const int n = bn + wn + nt*8 + cp;
                float2 v;
                v.x = acc[mt][nt][half*2 + 0];
                v.y = acc[mt][nt][half*2 + 1];
                if (MODE == 0) {
                    const int b = m >> 11, s = m & 2047;
                    const int part = n >> 10, hh = (n >> 6) & 15, dd = n & 63;
                    const size_t idx = (((size_t)(b*HEADS + hh))*SEQ + s)*HD + dd;
                    if (part == 0) {
                        *(__half2*)(g_Qf + idx) = __floats2half2_rn(v.x*QSCL, v.y*QSCL);
                    } else if (part == 1) {
                        *(__half2*)(g_Kf + idx) = __floats2half2_rn(v.x, v.y);
                    } else {
                        *(__half2*)(g_Vf + idx) = __floats2half2_rn(v.x, v.y);
                    }
                } else {
                    v.x += bias[n]; v.y += bias[n+1];
                    *(float2*)(out + (size_t)m * 1024 + n) = v;
                }
            }
        }
    }
}

/* ---------------- fp16 tensor-core flash attention (validated R11) ------ */
__global__ __launch_bounds__(256) void attn_tc()
{
    __shared__ char kvs[2][2][64*128];     /* [stage][K|V][64 rows x 128B] */

    const int tid = threadIdx.x, wid = tid >> 5, lane = tid & 31;
    const int g = lane >> 2, qd = lane & 3;
    const int bh = blockIdx.y;
    const int q0 = blockIdx.x * 128 + wid * 16;
    const size_t base = (size_t)bh * SEQ * HD;

    uint32_t qa[4][4];
    {
        const __half* Qp = g_Qf + base;
        const int r0 = q0 + g, r1 = q0 + g + 8;
#pragma unroll
        for (int ks = 0; ks < 4; ks++) {
            qa[ks][0] = *(const uint32_t*)(Qp + (size_t)r0*64 + ks*16 + 2*qd);
            qa[ks][1] = *(const uint32_t*)(Qp + (size_t)r1*64 + ks*16 + 2*qd);
            qa[ks][2] = *(const uint32_t*)(Qp + (size_t)r0*64 + ks*16 + 8 + 2*qd);
            qa[ks][3] = *(const uint32_t*)(Qp + (size_t)r1*64 + ks*16 + 8 + 2*qd);
        }
    }

    float o[8][4];
#pragma unroll
    for (int j = 0; j < 8; j++)
#pragma unroll
        for (int i = 0; i < 4; i++) o[j][i] = 0.f;
    float m0 = -1e30f, m1 = -1e30f, l0 = 0.f, l1 = 0.f;

    auto load_kv = [&](int s, int t) {
        const __half* Kg = g_Kf + base + (size_t)t * 64 * 64;
        const __half* Vg = g_Vf + base + (size_t)t * 64 * 64;
        const uint32_t kb = smem_u32(&kvs[s][0][0]);
        const uint32_t vb = smem_u32(&kvs[s][1][0]);
#pragma unroll
        for (int i = 0; i < 2; i++) {
            const int idx = tid + i * 256;
            const int r = idx >> 3, u = idx & 7;
            const uint32_t off = swz128((uint32_t)(r * 128 + u * 16));
            cp16(kb + off, Kg + r * 64 + u * 8);
            cp16(vb + off, Vg + r * 64 + u * 8);
        }
    };

    const int krow_in = (lane & 7) + ((lane >> 4) << 3);
    const uint32_t kunit = ((lane >> 3) & 1) * 16;
    const int vrow_in = (lane & 7) + (((lane >> 3) & 1) << 3);
    const uint32_t vunit = (lane >> 4) << 4;

    load_kv(0, 0);
    CP_COMMIT();

    for (int t = 0; t < SEQ/64; t++) {
        if (t + 1 < SEQ/64) {
            load_kv((t + 1) & 1, t + 1);
            CP_COMMIT();
            CP_WAIT(1);
        } else {
            CP_WAIT(0);
        }
        __syncthreads();

        const uint32_t kb = smem_u32(&kvs[t & 1][0][0]);
        const uint32_t vb = smem_u32(&kvs[t & 1][1][0]);

        float sc[8][4];
#pragma unroll
        for (int j = 0; j < 8; j++)
#pragma unroll
            for (int i = 0; i < 4; i++) sc[j][i] = 0.f;

#pragma unroll
        for (int ks = 0; ks < 4; ks++) {
#pragma unroll
            for (int nw = 0; nw < 4; nw++) {
                uint32_t b0, b1, b2, b3;
                const int row = nw * 16 + krow_in;
                const uint32_t addr = kb + swz128((uint32_t)(row*128 + ks*32) + kunit);
                ldm_x4(b0, b1, b2, b3, addr);
                mma_f16(sc[2*nw],   qa[ks], b0, b1);
                mma_f16(sc[2*nw+1], qa[ks], b2, b3);
            }
        }

        float mx0 = m0, mx1 = m1;
#pragma unroll
        for (int j = 0; j < 8; j++) {
            mx0 = fmaxf(mx0, fmaxf(sc[j][0], sc[j][1]));
            mx1 = fmaxf(mx1, fmaxf(sc[j][2], sc[j][3]));
        }
        mx0 = fmaxf(mx0, __shfl_xor_sync(0xffffffffu, mx0, 1));
        mx0 = fmaxf(mx0, __shfl_xor_sync(0xffffffffu, mx0, 2));
        mx1 = fmaxf(mx1, __shfl_xor_sync(0xffffffffu, mx1, 1));
        mx1 = fmaxf(mx1, __shfl_xor_sync(0xffffffffu, mx1, 2));

        const float c0 = exp2f(m0 - mx0);
        const float c1 = exp2f(m1 - mx1);
        m0 = mx0; m1 = mx1;
        l0 *= c0;  l1 *= c1;
#pragma unroll
        for (int j = 0; j < 8; j++) {
            o[j][0] *= c0; o[j][1] *= c0;
            o[j][2] *= c1; o[j][3] *= c1;
        }

        uint32_t pa[4][4];
        float s0 = 0.f, s1 = 0.f;
#pragma unroll
        for (int j = 0; j < 8; j++) {
            const float p0 = exp2f(sc[j][0] - m0);
            const float p1 = exp2f(sc[j][1] - m0);
            const float p2 = exp2f(sc[j][2] - m1);
            const float p3 = exp2f(sc[j][3] - m1);
            s0 += p0 + p1;  s1 += p2 + p3;
            const __half2 h01 = __floats2half2_rn(p0, p1);
            const __half2 h23 = __floats2half2_rn(p2, p3);
            const int kt = j >> 1;
            if ((j & 1) == 0) {
                pa[kt][0] = *(const uint32_t*)&h01;
                pa[kt][1] = *(const uint32_t*)&h23;
            } else {
                pa[kt][2] = *(const uint32_t*)&h01;
                pa[kt][3] = *(const uint32_t*)&h23;
            }
        }
        l0 += s0; l1 += s1;

#pragma unroll
        for (int kt = 0; kt < 4; kt++) {
#pragma unroll
            for (int nf = 0; nf < 4; nf++) {
                uint32_t v0, v1, v2, v3;
                const int row = kt * 16 + vrow_in;
                const uint32_t addr = vb + swz128((uint32_t)(row*128 + nf*32) + vunit);
                ldm_x4_t(v0, v1, v2, v3, addr);
                mma_f16(o[2*nf],   pa[kt], v0, v1);
                mma_f16(o[2*nf+1], pa[kt], v2, v3);
            }
        }
        __syncthreads();
    }

    l0 += __shfl_xor_sync(0xffffffffu, l0, 1);
    l0 += __shfl_xor_sync(0xffffffffu, l0, 2);
    l1 += __shfl_xor_sync(0xffffffffu, l1, 1);
    l1 += __shfl_xor_sync(0xffffffffu, l1, 2);
    const float inv0 = 1.f / l0, inv1 = 1.f / l1;

    const int b = bh >> 4, h = bh & 15;
    const int row0 = q0 + g, row1 = q0 + g + 8;
    __half* A0 = g_Af + ((size_t)(b*SEQ + row0))*EMBED + h*HD;
    __half* A1 = g_Af + ((size_t)(b*SEQ + row1))*EMBED + h*HD;
#pragma unroll
    for (int j = 0; j < 8; j++) {
        const int d = j*8 + 2*qd;
        *(__half2*)(A0 + d) = __floats2half2_rn(o[j][0]*inv0, o[j][1]*inv0);
        *(__half2*)(A1 + d) = __floats2half2_rn(o[j][2]*inv1, o[j][3]*inv1);
    }
}

/* ---------------- launch ------------------------------------------------ */
extern "C" void kernel_launch(void* const* d_in, const int* in_sizes, int n_in,
                              void* d_out, int out_size)
{
    const float* x      = (const float*)d_in[0];
    /* d_in[1] = xpos (unused) */
    const float* qkv_w  = (const float*)d_in[2];
    const float* proj_w = (const float*)d_in[3];
    const float* proj_b = (const float*)d_in[4];
    float* out = (float*)d_out;

    conv_all<<<1184, 256>>>(x, qkv_w, proj_w);

    dim3 gq(NQKV/128, MROWS/128);          /* 24 x 32 */
    gemm_mma<0><<<gq, 256, 2*2*TILE_B>>>(nullptr, nullptr);

    dim3 ga(SEQ/128, BATCH*HEADS);         /* 16 x 32 */
    attn_tc<<<ga, 256>>>();

    dim3 gp(EMBED/128, MROWS/128);         /* 8 x 32 */
    gemm_mma<1><<<gp, 256, 2*3*TILE_B>>>(proj_b, out);
}

// round 16
// speedup vs baseline: 8.9958x; 1.0573x over previous
#include <cuda_runtime.h>
#include <cuda_bf16.h>
#include <cuda_fp16.h>
#include <cstdint>
#include <math.h>

#define EMBED   1024
#define HEADS   16
#define HD      64
#define BATCH   2
#define SEQ     2048
#define MROWS   (BATCH*SEQ)       /* 4096 */
#define NQKV    (3*EMBED)         /* 3072 */
#define LOG2E   1.44269504088896f

/* ---------------- scratch (__device__ globals) ------------------------- */
__device__ __half g_Qf[BATCH*HEADS*SEQ*HD];   /* pre-scaled by 0.125*log2e */
__device__ __half g_Kf[BATCH*HEADS*SEQ*HD];
__device__ __half g_Vf[BATCH*HEADS*SEQ*HD];

__device__ __half g_Xf[MROWS*EMBED];          /* activations, fp16 */
__device__ __half g_Af[MROWS*EMBED];          /* attention output, fp16 */
__device__ __half g_Wh[NQKV*EMBED];           /* qkv_w, fp16 */
__device__ __half g_Ph[EMBED*EMBED];          /* proj_w, fp16 */

/* ---------------- helpers ---------------------------------------------- */
__device__ __forceinline__ uint32_t smem_u32(const void* p) {
    uint32_t a;
    asm("{ .reg .u64 t; cvta.to.shared.u64 t, %1; cvt.u32.u64 %0, t; }"
        : "=r"(a) : "l"(p));
    return a;
}
__device__ __forceinline__ void cp16(uint32_t dst, const void* src) {
    asm volatile("cp.async.cg.shared.global [%0], [%1], 16;" :: "r"(dst), "l"(src));
}
#define CP_COMMIT() asm volatile("cp.async.commit_group;" ::: "memory")
#define CP_WAIT(n)  asm volatile("cp.async.wait_group %0;" :: "n"(n) : "memory")

__device__ __forceinline__ void ldm_x4(uint32_t& r0, uint32_t& r1,
                                       uint32_t& r2, uint32_t& r3, uint32_t addr) {
    asm volatile("ldmatrix.sync.aligned.m8n8.x4.shared.b16 {%0,%1,%2,%3}, [%4];"
                 : "=r"(r0), "=r"(r1), "=r"(r2), "=r"(r3) : "r"(addr));
}
__device__ __forceinline__ void ldm_x4_t(uint32_t& r0, uint32_t& r1,
                                         uint32_t& r2, uint32_t& r3, uint32_t addr) {
    asm volatile("ldmatrix.sync.aligned.m8n8.x4.trans.shared.b16 {%0,%1,%2,%3}, [%4];"
                 : "=r"(r0), "=r"(r1), "=r"(r2), "=r"(r3) : "r"(addr));
}
__device__ __forceinline__ void mma_f16(float* c, const uint32_t* a,
                                        uint32_t b0, uint32_t b1) {
    asm volatile("mma.sync.aligned.m16n8k16.row.col.f32.f16.f16.f32 "
                 "{%0,%1,%2,%3}, {%4,%5,%6,%7}, {%8,%9}, {%0,%1,%2,%3};"
                 : "+f"(c[0]), "+f"(c[1]), "+f"(c[2]), "+f"(c[3])
                 : "r"(a[0]), "r"(a[1]), "r"(a[2]), "r"(a[3]), "r"(b0), "r"(b1));
}
__device__ __forceinline__ uint32_t swz64(uint32_t o)  { return o ^ ((o >> 3) & 0x30); }
__device__ __forceinline__ uint32_t swz128(uint32_t o) { return o ^ ((o >> 3) & 0x70); }

/* ---------------- fused conversion kernel ------------------------------- */
#define NX (MROWS*EMBED/4)
#define NW (NQKV*EMBED/4)
#define NP (EMBED*EMBED/4)
__global__ __launch_bounds__(256) void conv_all(const float* __restrict__ x,
                                                const float* __restrict__ qkv_w,
                                                const float* __restrict__ proj_w)
{
    for (int i = blockIdx.x * 256 + threadIdx.x; i < NX + NW + NP;
         i += gridDim.x * 256) {
        const float4* src;
        __half2* dst;
        int j;
        if (i < NX)           { src = (const float4*)x;      dst = (__half2*)g_Xf; j = i; }
        else if (i < NX + NW) { src = (const float4*)qkv_w;  dst = (__half2*)g_Wh; j = i - NX; }
        else                  { src = (const float4*)proj_w; dst = (__half2*)g_Ph; j = i - NX - NW; }
        float4 v = src[j];
        dst[j*2+0] = __floats2half2_rn(v.x, v.y);
        dst[j*2+1] = __floats2half2_rn(v.z, v.w);
    }
}

/* ---------------- warp-MMA fp16 GEMM (3-stage pipeline) ----------------- */
/* C[m,n] = sum_k A[m,k]*W[n,k]; K=1024; BK=32; stage = A+B = 16KB; x3.    */
#define BK      32
#define NCHG    (1024/BK)              /* 32 */
#define TILE_B  8192
#define STAGE   (2*TILE_B)             /* 16KB */
#define GEMM_SMEM (3*STAGE)            /* 49152 */

template<int MODE>
__global__ __launch_bounds__(256) void gemm_mma(const float* __restrict__ bias,
                                                float* __restrict__ out)
{
    extern __shared__ char smem_raw[];
    const int tid = threadIdx.x, wid = tid >> 5, lane = tid & 31;
    const int bm = blockIdx.y * 128, bn = blockIdx.x * 128;

    const __half* Ap = (MODE == 0) ? g_Xf : g_Af;
    const __half* Bp = (MODE == 0) ? g_Wh : g_Ph;

    const uint32_t sbase = smem_u32(smem_raw);

    const int lr0 = tid >> 2;               /* rows 0..63 (i=0) */
    const int lu  = tid & 3;                /* 16B unit 0..3    */

    const int wm = (wid >> 2) * 64;
    const int wn = (wid & 3) * 32;

    const int a_r = wm + (lane & 15);
    const int b_r = wn + (lane & 7) + ((lane >> 4) << 3);
    const uint32_t a_base = (uint32_t)(a_r * 64 + ((lane >> 4) << 4));
    const uint32_t b_base = (uint32_t)(b_r * 64 + (((lane >> 3) & 1) << 4));

    float acc[4][4][4];
#pragma unroll
    for (int mt = 0; mt < 4; mt++)
#pragma unroll
        for (int nt = 0; nt < 4; nt++)
#pragma unroll
            for (int i = 0; i < 4; i++) acc[mt][nt][i] = 0.f;

    auto load_chunk = [&](int stage, int k0) {
        const uint32_t sb = sbase + stage * STAGE;
#pragma unroll
        for (int i = 0; i < 2; i++) {
            const int r = lr0 + i * 64;
            const uint32_t so = swz64((uint32_t)(r * 64 + lu * 16));
            cp16(sb + so,          Ap + (size_t)(bm + r) * 1024 + k0 + lu * 8);
            cp16(sb + TILE_B + so, Bp + (size_t)(bn + r) * 1024 + k0 + lu * 8);
        }
    };

    load_chunk(0, 0);
    CP_COMMIT();
    load_chunk(1, BK);
    CP_COMMIT();

    int stage = 0;
    for (int c = 0; c < NCHG; c++) {
        if (c + 2 < NCHG) {
            int s2 = stage + 2;            /* ring: (stage+2) mod 3 */
            if (s2 >= 3) s2 -= 3;
            load_chunk(s2, (c + 2) * BK);
            CP_COMMIT();
            CP_WAIT(2);
        } else if (c + 1 < NCHG) {
            CP_WAIT(1);
        } else {
            CP_WAIT(0);
        }
        __syncthreads();

        const uint32_t sb = sbase + stage * STAGE;
#pragma unroll
        for (int ks = 0; ks < 2; ks++) {
            uint32_t ah[4][4], bh[2][4];
#pragma unroll
            for (int mt = 0; mt < 4; mt++) {
                const uint32_t off = swz64(a_base + (uint32_t)(mt*16*64 + ks*32));
                ldm_x4(ah[mt][0], ah[mt][1], ah[mt][2], ah[mt][3], sb + off);
            }
#pragma unroll
            for (int np = 0; np < 2; np++) {
                const uint32_t off = swz64(b_base + (uint32_t)(np*16*64 + ks*32));
                ldm_x4(bh[np][0], bh[np][1], bh[np][2], bh[np][3], sb + TILE_B + off);
            }
#pragma unroll
            for (int mt = 0; mt < 4; mt++)
#pragma unroll
                for (int nt = 0; nt < 4; nt++) {
                    const int np = nt >> 1, h = (nt & 1) * 2;
                    mma_f16(acc[mt][nt], ah[mt], bh[np][h], bh[np][h+1]);
                }
        }
        __syncthreads();
        stage = (stage == 2) ? 0 : stage + 1;
    }

    const int gr = lane >> 2, cp = (lane & 3) * 2;
    const float QSCL = 0.125f * LOG2E;
#pragma unroll
    for (int mt = 0; mt < 4; mt++) {
        const int m0 = bm + wm + mt*16 + gr;
#pragma unroll
        for (int half = 0; half < 2; half++) {
            const int m = m0 + half * 8;
#pragma unroll
            for (int nt = 0; nt < 4; nt++) {
                const int n = bn + wn + nt*8 + cp;
                float2 v;
                v.x = acc[mt][nt][half*2 + 0];
                v.y = acc[mt][nt][half*2 + 1];
                if (MODE == 0) {
                    const int b = m >> 11, s = m & 2047;
                    const int part = n >> 10, hh = (n >> 6) & 15, dd = n & 63;
                    const size_t idx = (((size_t)(b*HEADS + hh))*SEQ + s)*HD + dd;
                    if (part == 0) {
                        *(__half2*)(g_Qf + idx) = __floats2half2_rn(v.x*QSCL, v.y*QSCL);
                    } else if (part == 1) {
                        *(__half2*)(g_Kf + idx) = __floats2half2_rn(v.x, v.y);
                    } else {
                        *(__half2*)(g_Vf + idx) = __floats2half2_rn(v.x, v.y);
                    }
                } else {
                    v.x += bias[n]; v.y += bias[n+1];
                    *(float2*)(out + (size_t)m * 1024 + n) = v;
                }
            }
        }
    }
}

/* ---------------- fp16 tensor-core flash attention (validated R11) ------ */
__global__ __launch_bounds__(256) void attn_tc()
{
    __shared__ char kvs[2][2][64*128];     /* [stage][K|V][64 rows x 128B] */

    const int tid = threadIdx.x, wid = tid >> 5, lane = tid & 31;
    const int g = lane >> 2, qd = lane & 3;
    const int bh = blockIdx.y;
    const int q0 = blockIdx.x * 128 + wid * 16;
    const size_t base = (size_t)bh * SEQ * HD;

    uint32_t qa[4][4];
    {
        const __half* Qp = g_Qf + base;
        const int r0 = q0 + g, r1 = q0 + g + 8;
#pragma unroll
        for (int ks = 0; ks < 4; ks++) {
            qa[ks][0] = *(const uint32_t*)(Qp + (size_t)r0*64 + ks*16 + 2*qd);
            qa[ks][1] = *(const uint32_t*)(Qp + (size_t)r1*64 + ks*16 + 2*qd);
            qa[ks][2] = *(const uint32_t*)(Qp + (size_t)r0*64 + ks*16 + 8 + 2*qd);
            qa[ks][3] = *(const uint32_t*)(Qp + (size_t)r1*64 + ks*16 + 8 + 2*qd);
        }
    }

    float o[8][4];
#pragma unroll
    for (int j = 0; j < 8; j++)
#pragma unroll
        for (int i = 0; i < 4; i++) o[j][i] = 0.f;
    float m0 = -1e30f, m1 = -1e30f, l0 = 0.f, l1 = 0.f;

    auto load_kv = [&](int s, int t) {
        const __half* Kg = g_Kf + base + (size_t)t * 64 * 64;
        const __half* Vg = g_Vf + base + (size_t)t * 64 * 64;
        const uint32_t kb = smem_u32(&kvs[s][0][0]);
        const uint32_t vb = smem_u32(&kvs[s][1][0]);
#pragma unroll
        for (int i = 0; i < 2; i++) {
            const int idx = tid + i * 256;
            const int r = idx >> 3, u = idx & 7;
            const uint32_t off = swz128((uint32_t)(r * 128 + u * 16));
            cp16(kb + off, Kg + r * 64 + u * 8);
            cp16(vb + off, Vg + r * 64 + u * 8);
        }
    };

    const int krow_in = (lane & 7) + ((lane >> 4) << 3);
    const uint32_t kunit = ((lane >> 3) & 1) * 16;
    const int vrow_in = (lane & 7) + (((lane >> 3) & 1) << 3);
    const uint32_t vunit = (lane >> 4) << 4;

    load_kv(0, 0);
    CP_COMMIT();

    for (int t = 0; t < SEQ/64; t++) {
        if (t + 1 < SEQ/64) {
            load_kv((t + 1) & 1, t + 1);
            CP_COMMIT();
            CP_WAIT(1);
        } else {
            CP_WAIT(0);
        }
        __syncthreads();

        const uint32_t kb = smem_u32(&kvs[t & 1][0][0]);
        const uint32_t vb = smem_u32(&kvs[t & 1][1][0]);

        float sc[8][4];
#pragma unroll
        for (int j = 0; j < 8; j++)
#pragma unroll
            for (int i = 0; i < 4; i++) sc[j][i] = 0.f;

#pragma unroll
        for (int ks = 0; ks < 4; ks++) {
#pragma unroll
            for (int nw = 0; nw < 4; nw++) {
                uint32_t b0, b1, b2, b3;
                const int row = nw * 16 + krow_in;
                const uint32_t addr = kb + swz128((uint32_t)(row*128 + ks*32) + kunit);
                ldm_x4(b0, b1, b2, b3, addr);
                mma_f16(sc[2*nw],   qa[ks], b0, b1);
                mma_f16(sc[2*nw+1], qa[ks], b2, b3);
            }
        }

        float mx0 = m0, mx1 = m1;
#pragma unroll
        for (int j = 0; j < 8; j++) {
            mx0 = fmaxf(mx0, fmaxf(sc[j][0], sc[j][1]));
            mx1 = fmaxf(mx1, fmaxf(sc[j][2], sc[j][3]));
        }
        mx0 = fmaxf(mx0, __shfl_xor_sync(0xffffffffu, mx0, 1));
        mx0 = fmaxf(mx0, __shfl_xor_sync(0xffffffffu, mx0, 2));
        mx1 = fmaxf(mx1, __shfl_xor_sync(0xffffffffu, mx1, 1));
        mx1 = fmaxf(mx1, __shfl_xor_sync(0xffffffffu, mx1, 2));

        const float c0 = exp2f(m0 - mx0);
        const float c1 = exp2f(m1 - mx1);
        m0 = mx0; m1 = mx1;
        l0 *= c0;  l1 *= c1;
#pragma unroll
        for (int j = 0; j < 8; j++) {
            o[j][0] *= c0; o[j][1] *= c0;
            o[j][2] *= c1; o[j][3] *= c1;
        }

        uint32_t pa[4][4];
        float s0 = 0.f, s1 = 0.f;
#pragma unroll
        for (int j = 0; j < 8; j++) {
            const float p0 = exp2f(sc[j][0] - m0);
            const float p1 = exp2f(sc[j][1] - m0);
            const float p2 = exp2f(sc[j][2] - m1);
            const float p3 = exp2f(sc[j][3] - m1);
            s0 += p0 + p1;  s1 += p2 + p3;
            const __half2 h01 = __floats2half2_rn(p0, p1);
            const __half2 h23 = __floats2half2_rn(p2, p3);
            const int kt = j >> 1;
            if ((j & 1) == 0) {
                pa[kt][0] = *(const uint32_t*)&h01;
                pa[kt][1] = *(const uint32_t*)&h23;
            } else {
                pa[kt][2] = *(const uint32_t*)&h01;
                pa[kt][3] = *(const uint32_t*)&h23;
            }
        }
        l0 += s0; l1 += s1;

#pragma unroll
        for (int kt = 0; kt < 4; kt++) {
#pragma unroll
            for (int nf = 0; nf < 4; nf++) {
                uint32_t v0, v1, v2, v3;
                const int row = kt * 16 + vrow_in;
                const uint32_t addr = vb + swz128((uint32_t)(row*128 + nf*32) + vunit);
                ldm_x4_t(v0, v1, v2, v3, addr);
                mma_f16(o[2*nf],   pa[kt], v0, v1);
                mma_f16(o[2*nf+1], pa[kt], v2, v3);
            }
        }
        __syncthreads();
    }

    l0 += __shfl_xor_sync(0xffffffffu, l0, 1);
    l0 += __shfl_xor_sync(0xffffffffu, l0, 2);
    l1 += __shfl_xor_sync(0xffffffffu, l1, 1);
    l1 += __shfl_xor_sync(0xffffffffu, l1, 2);
    const float inv0 = 1.f / l0, inv1 = 1.f / l1;

    const int b = bh >> 4, h = bh & 15;
    const int row0 = q0 + g, row1 = q0 + g + 8;
    __half* A0 = g_Af + ((size_t)(b*SEQ + row0))*EMBED + h*HD;
    __half* A1 = g_Af + ((size_t)(b*SEQ + row1))*EMBED + h*HD;
#pragma unroll
    for (int j = 0; j < 8; j++) {
        const int d = j*8 + 2*qd;
        *(__half2*)(A0 + d) = __floats2half2_rn(o[j][0]*inv0, o[j][1]*inv0);
        *(__half2*)(A1 + d) = __floats2half2_rn(o[j][2]*inv1, o[j][3]*inv1);
    }
}

/* ---------------- launch ------------------------------------------------ */
extern "C" void kernel_launch(void* const* d_in, const int* in_sizes, int n_in,
                              void* d_out, int out_size)
{
    const float* x      = (const float*)d_in[0];
    /* d_in[1] = xpos (unused) */
    const float* qkv_w  = (const float*)d_in[2];
    const float* proj_w = (const float*)d_in[3];
    const float* proj_b = (const float*)d_in[4];
    float* out = (float*)d_out;

    conv_all<<<1184, 256>>>(x, qkv_w, proj_w);

    dim3 gq(NQKV/128, MROWS/128);          /* 24 x 32 */
    gemm_mma<0><<<gq, 256, GEMM_SMEM>>>(nullptr, nullptr);

    dim3 ga(SEQ/128, BATCH*HEADS);         /* 16 x 32 */
    attn_tc<<<ga, 256>>>();

    dim3 gp(EMBED/128, MROWS/128);         /* 8 x 32 */
    gemm_mma<1><<<gp, 256, GEMM_SMEM>>>(proj_b, out);
}